// round 11
// baseline (speedup 1.0000x reference)
#include <cuda_runtime.h>
#include <cuda_bf16.h>
#include <mma.h>
#include <cstdint>
#include <cstddef>

using namespace nvcuda;

#define TT 511          // T-1 rows
#define VV 32000
#define EE 512
#define HH 512
#define SPLITS 25
#define KCHUNK 1280     // 32000 / 25

// ---------------- scratch (__device__ globals; no allocation) ----------------
__device__ float g_part[SPLITS * 512 * 512];
__device__ float g_emb[TT * EE];
__device__ float g_xproj[TT * HH];
__device__ float g_hs[TT * HH];
__device__ float g_logits[(size_t)512 * VV];     // padded to 512 rows for wmma store
__device__ __nv_bfloat16 g_wp_h[(size_t)VV * 512];
__device__ __nv_bfloat16 g_wp_l[(size_t)VV * 512];
__device__ __nv_bfloat16 g_hs_h[512 * 512];      // padded to 512 rows (zeros)
__device__ __nv_bfloat16 g_hs_l[512 * 512];

// ---------------- f32x2 helpers ----------------
__device__ __forceinline__ void fma2(unsigned long long& d, unsigned long long a,
                                     unsigned long long b) {
    asm("fma.rn.f32x2 %0, %1, %2, %0;" : "+l"(d) : "l"(a), "l"(b));
}
__device__ __forceinline__ unsigned long long dup2(float x) {
    unsigned long long d;
    asm("mov.b64 %0, {%1, %1};" : "=l"(d) : "f"(x));
    return d;
}
__device__ __forceinline__ float2 unpack2(unsigned long long d) {
    float2 r;
    asm("mov.b64 {%0, %1}, %2;" : "=f"(r.x), "=f"(r.y) : "l"(d));
    return r;
}

// ---------------- 128x128 NT fp32 GEMM (GEMM1), double-buffered, occ 2 ----------
__global__ void __launch_bounds__(256, 2)
gemm_nt128(const float* __restrict__ A, int lda,
           const float* __restrict__ B, int ldb,
           float* __restrict__ C, int ldc, size_t zStride,
           int M, int kLen)
{
    __shared__ float As[2][16][132];
    __shared__ float Bs[2][16][132];
    const int tid = threadIdx.x;
    const int nt = blockIdx.x, mt = blockIdx.y, sz = blockIdx.z;
    const int kOff = sz * kLen;
    float* Cz = C + (size_t)sz * zStride;
    const int ty = tid >> 4, tx = tid & 15;
    const int m0 = ty * 8, n0 = tx * 8;

    int lm[2], lk4[2], ra[2], rb[2];
    bool aok[2];
#pragma unroll
    for (int i = 0; i < 2; i++) {
        int idx = tid + i * 256;
        lm[i] = idx >> 2;
        lk4[i] = (idx & 3) << 2;
        ra[i] = mt * 128 + lm[i];
        rb[i] = nt * 128 + lm[i];
        aok[i] = (ra[i] < M);
    }

    unsigned long long acc[8][4];
#pragma unroll
    for (int i = 0; i < 8; i++)
#pragma unroll
        for (int j = 0; j < 4; j++) acc[i][j] = 0ull;

#pragma unroll
    for (int i = 0; i < 2; i++) {
        size_t gk = (size_t)(kOff + lk4[i]);
        float4 va = aok[i] ? *(const float4*)(A + (size_t)ra[i] * lda + gk)
                           : make_float4(0.f, 0.f, 0.f, 0.f);
        float4 vb = *(const float4*)(B + (size_t)rb[i] * ldb + gk);
        int m = lm[i], k4 = lk4[i];
        As[0][k4 + 0][m] = va.x; As[0][k4 + 1][m] = va.y;
        As[0][k4 + 2][m] = va.z; As[0][k4 + 3][m] = va.w;
        Bs[0][k4 + 0][m] = vb.x; Bs[0][k4 + 1][m] = vb.y;
        Bs[0][k4 + 2][m] = vb.z; Bs[0][k4 + 3][m] = vb.w;
    }
    __syncthreads();

    int cur = 0;
    for (int kb = 0; kb < kLen; kb += 16) {
        const bool has_next = (kb + 16 < kLen);
        float4 pa[2], pb[2];
        if (has_next) {
#pragma unroll
            for (int i = 0; i < 2; i++) {
                size_t gk = (size_t)(kOff + kb + 16 + lk4[i]);
                pa[i] = aok[i] ? *(const float4*)(A + (size_t)ra[i] * lda + gk)
                               : make_float4(0.f, 0.f, 0.f, 0.f);
                pb[i] = *(const float4*)(B + (size_t)rb[i] * ldb + gk);
            }
        }
#pragma unroll
        for (int k = 0; k < 16; k++) {
            float4 a0 = *(const float4*)&As[cur][k][m0];
            float4 a1 = *(const float4*)&As[cur][k][m0 + 4];
            ulonglong2 b0 = *(const ulonglong2*)&Bs[cur][k][n0];
            ulonglong2 b1 = *(const ulonglong2*)&Bs[cur][k][n0 + 4];
            float av[8] = {a0.x, a0.y, a0.z, a0.w, a1.x, a1.y, a1.z, a1.w};
#pragma unroll
            for (int i = 0; i < 8; i++) {
                unsigned long long ad = dup2(av[i]);
                fma2(acc[i][0], ad, b0.x);
                fma2(acc[i][1], ad, b0.y);
                fma2(acc[i][2], ad, b1.x);
                fma2(acc[i][3], ad, b1.y);
            }
        }
        if (has_next) {
            int nb = cur ^ 1;
#pragma unroll
            for (int i = 0; i < 2; i++) {
                int m = lm[i], k4 = lk4[i];
                As[nb][k4 + 0][m] = pa[i].x; As[nb][k4 + 1][m] = pa[i].y;
                As[nb][k4 + 2][m] = pa[i].z; As[nb][k4 + 3][m] = pa[i].w;
                Bs[nb][k4 + 0][m] = pb[i].x; Bs[nb][k4 + 1][m] = pb[i].y;
                Bs[nb][k4 + 2][m] = pb[i].z; Bs[nb][k4 + 3][m] = pb[i].w;
            }
        }
        __syncthreads();
        cur ^= 1;
    }
#pragma unroll
    for (int i = 0; i < 8; i++) {
        int r = mt * 128 + m0 + i;
        if (r >= M) continue;
        float* cp = Cz + (size_t)r * ldc + nt * 128 + n0;
#pragma unroll
        for (int j = 0; j < 4; j++) {
            float2 v = unpack2(acc[i][j]);
            cp[2 * j] = v.x;
            cp[2 * j + 1] = v.y;
        }
    }
}

// ---------------- reduce split-K partials into emb ----------------
__global__ void reduce_emb_kernel()
{
    int i = blockIdx.x * 256 + threadIdx.x;
    if (i >= TT * EE) return;
    float s = 0.f;
#pragma unroll
    for (int p = 0; p < SPLITS; p++) s += g_part[p * (512 * 512) + i];
    g_emb[i] = s;
}

// ---------------- xproj = emb @ W_x^T + b ----------------
__global__ void __launch_bounds__(256)
xproj_kernel(const float* __restrict__ W_x, const float* __restrict__ bias)
{
    __shared__ float As[16][68];
    __shared__ float Bs[16][68];
    const int tid = threadIdx.x;
    const int nt = blockIdx.x, mt = blockIdx.y;
    const int ty = tid >> 4, tx = tid & 15;
    const int m0 = ty * 4, n0 = tx * 4;
    float acc[4][4] = {};

    for (int kb = 0; kb < 512; kb += 16) {
        int m = tid >> 2, k4 = (tid & 3) << 2;
        float4 va = make_float4(0.f, 0.f, 0.f, 0.f);
        int ra = mt * 64 + m;
        if (ra < TT) va = *(const float4*)(g_emb + (size_t)ra * 512 + kb + k4);
        As[k4 + 0][m] = va.x; As[k4 + 1][m] = va.y;
        As[k4 + 2][m] = va.z; As[k4 + 3][m] = va.w;
        float4 vb = *(const float4*)(W_x + (size_t)(nt * 64 + m) * 512 + kb + k4);
        Bs[k4 + 0][m] = vb.x; Bs[k4 + 1][m] = vb.y;
        Bs[k4 + 2][m] = vb.z; Bs[k4 + 3][m] = vb.w;
        __syncthreads();
#pragma unroll
        for (int k = 0; k < 16; k++) {
            float4 a = *(const float4*)&As[k][m0];
            float4 b = *(const float4*)&Bs[k][n0];
            float aa[4] = {a.x, a.y, a.z, a.w};
            float bb[4] = {b.x, b.y, b.z, b.w};
#pragma unroll
            for (int i = 0; i < 4; i++)
#pragma unroll
                for (int j = 0; j < 4; j++) acc[i][j] += aa[i] * bb[j];
        }
        __syncthreads();
    }
#pragma unroll
    for (int i = 0; i < 4; i++) {
        int r = mt * 64 + m0 + i;
        if (r >= TT) continue;
#pragma unroll
        for (int j = 0; j < 4; j++) {
            int col = nt * 64 + n0 + j;
            g_xproj[(size_t)r * 512 + col] = acc[i][j] + bias[col];
        }
    }
}

// ---------------- Elman recurrence: EXACT R1 version (measured ~621us) ----------
__global__ void __cluster_dims__(8, 1, 1) __launch_bounds__(1024, 1)
rnn_kernel(const float* __restrict__ W_h)
{
    __shared__ float hbuf[2][512];
    __shared__ float pbuf[64][17];
    const int tid = threadIdx.x;
    const int w = tid >> 5, l = tid & 31;
    const int g = w & 1, s = w >> 1;
    const int c = (int)blockIdx.x;
    const int row = c * 64 + g * 32 + l;
    const int kbase = s * 32;

    ulonglong2 wv[8];
    {
        const ulonglong2* wp = (const ulonglong2*)(W_h + (size_t)row * 512 + kbase);
#pragma unroll
        for (int j = 0; j < 8; j++) wv[j] = wp[j];
    }
    for (int i = tid; i < 512; i += 1024) hbuf[0][i] = 0.f;

    uint32_t hbase_local = (uint32_t)__cvta_generic_to_shared(&hbuf[0][0]);
    uint32_t peer[8];
#pragma unroll
    for (int p = 0; p < 8; p++)
        asm("mapa.shared::cluster.u32 %0, %1, %2;" : "=r"(peer[p]) : "r"(hbase_local), "r"(p));

    float xp = (tid < 64) ? g_xproj[(size_t)c * 64 + tid] : 0.f;

    __syncthreads();
    asm volatile("barrier.cluster.arrive.aligned;" ::: "memory");
    asm volatile("barrier.cluster.wait.aligned;" ::: "memory");

    for (int t = 0; t < TT; t++) {
        const int cur = t & 1;
        const ulonglong2* hp = (const ulonglong2*)&hbuf[cur][kbase];
        unsigned long long acc = 0ull;
#pragma unroll
        for (int j = 0; j < 8; j++) {
            ulonglong2 hh = hp[j];
            fma2(acc, wv[j].x, hh.x);
            fma2(acc, wv[j].y, hh.y);
        }
        float2 f = unpack2(acc);
        pbuf[g * 32 + l][s] = f.x + f.y;
        __syncthreads();
        if (tid < 64) {
            float x = xp;
#pragma unroll
            for (int s2 = 0; s2 < 16; s2++) x += pbuf[tid][s2];
            float h = 1.f / (1.f + __expf(-x));
            g_hs[(size_t)t * 512 + c * 64 + tid] = h;
            uint32_t off = (uint32_t)(((cur ^ 1) * 512 + c * 64 + tid) * 4);
#pragma unroll
            for (int p = 0; p < 8; p++)
                asm volatile("st.shared::cluster.f32 [%0], %1;"
                             :: "r"(peer[p] + off), "f"(h) : "memory");
            int tn = (t + 1 < TT) ? (t + 1) : t;
            xp = g_xproj[(size_t)tn * 512 + c * 64 + tid];
        }
        asm volatile("barrier.cluster.arrive.aligned;" ::: "memory");
        asm volatile("barrier.cluster.wait.aligned;" ::: "memory");
    }
}

// ---------------- bf16 hi/lo splits ----------------
__global__ void prep_wp_kernel(const float* __restrict__ W_p)
{
    size_t i = (size_t)blockIdx.x * 1024 + threadIdx.x;
    if (i >= (size_t)VV * 512) return;
    float v = W_p[i];
    __nv_bfloat16 h = __float2bfloat16_rn(v);
    g_wp_h[i] = h;
    g_wp_l[i] = __float2bfloat16_rn(v - __bfloat162float(h));
}
__global__ void prep_hs_kernel()
{
    int i = blockIdx.x * 1024 + threadIdx.x;
    if (i >= 512 * 512) return;
    float v = (i < TT * 512) ? g_hs[i] : 0.f;
    __nv_bfloat16 h = __float2bfloat16_rn(v);
    g_hs_h[i] = h;
    g_hs_l[i] = __float2bfloat16_rn(v - __bfloat162float(h));
}

// ---------------- GEMM2 via WMMA bf16 3-pass + cp.async pipeline ----------------
// CTA tile 128(M) x 256(N), 8 warps in 2x4, warp tile 64x64 (4x4 acc frags).
// 3 passes (hh, hl, lh). K chunks of 32, DEPTH-2 cp.async pipeline: chunk c+2's
// loads stream into the buffer freed by chunk c while chunk c+1 computes.
// Dynamic smem: 2 buffers x (Ah/Al [128][48] + Bh/Bl [256][48]) bf16 = 147456 B.
#define G2_LD 48
#define G2_A_SZ (128 * G2_LD)                        // elems per A split
#define G2_B_SZ (256 * G2_LD)
#define G2_BUF_ELEMS (2 * G2_A_SZ + 2 * G2_B_SZ)     // 36864 elems = 73728 B
#define G2_SMEM (2 * G2_BUF_ELEMS * 2)               // 147456 bytes

__device__ __forceinline__ void cp_async16(uint32_t dst, const void* src) {
    asm volatile("cp.async.cg.shared.global [%0], [%1], 16;"
                 :: "r"(dst), "l"(src));
}

__global__ void __launch_bounds__(256, 1)
gemm2_wmma(float* __restrict__ C)
{
    extern __shared__ __align__(32) __nv_bfloat16 sm2[];
    const uint32_t sbase = (uint32_t)__cvta_generic_to_shared(sm2);
    const __nv_bfloat16* Agm[2] = { g_hs_h, g_hs_l };
    const __nv_bfloat16* Bgm[2] = { g_wp_h, g_wp_l };

    const int tid = threadIdx.x;
    const int wid = tid >> 5;
    const int warp_m = wid >> 2;          // 0..1
    const int warp_n = wid & 3;           // 0..3
    const int nt = blockIdx.x, mt = blockIdx.y;
    const int arow = mt * 128, brow = nt * 256;

    // per-thread load geometry (fixed): A 4 items, B 8 items of 16B
    int a_s[4], a_off[4];
    const __nv_bfloat16* a_src[4];
#pragma unroll
    for (int i = 0; i < 4; i++) {
        int lin = tid + i * 256;
        int s = lin >> 9, rem = lin & 511;
        int r = rem >> 2, seg = rem & 3;
        a_s[i] = s;
        a_off[i] = s * G2_A_SZ + r * G2_LD + seg * 8;
        a_src[i] = Agm[s] + (size_t)(arow + r) * 512 + seg * 8;
    }
    int b_off[8];
    const __nv_bfloat16* b_src[8];
#pragma unroll
    for (int i = 0; i < 8; i++) {
        int lin = tid + i * 256;
        int s = lin >> 10, rem = lin & 1023;
        int r = rem >> 2, seg = rem & 3;
        b_off[i] = 2 * G2_A_SZ + s * G2_B_SZ + r * G2_LD + seg * 8;
        b_src[i] = Bgm[s] + (size_t)(brow + r) * 512 + seg * 8;
    }

    auto issue_chunk = [&](int buf, int kc) {
        uint32_t base = sbase + (uint32_t)(buf * G2_BUF_ELEMS) * 2;
#pragma unroll
        for (int i = 0; i < 4; i++)
            cp_async16(base + (uint32_t)a_off[i] * 2, a_src[i] + kc);
#pragma unroll
        for (int i = 0; i < 8; i++)
            cp_async16(base + (uint32_t)b_off[i] * 2, b_src[i] + kc);
        asm volatile("cp.async.commit_group;" ::: "memory");
    };

    wmma::fragment<wmma::accumulator, 16, 16, 16, float> acc[4][4];
#pragma unroll
    for (int mi = 0; mi < 4; mi++)
#pragma unroll
        for (int ni = 0; ni < 4; ni++) wmma::fill_fragment(acc[mi][ni], 0.f);

    // prologue: chunks 0 and 1 in flight
    issue_chunk(0, 0);
    issue_chunk(1, 32);

    for (int c = 0; c < 16; c++) {
        const int buf = c & 1;
        if (c < 14)
            asm volatile("cp.async.wait_group 1;" ::: "memory");
        else
            asm volatile("cp.async.wait_group 0;" ::: "memory");
        __syncthreads();                 // chunk c's data visible to all warps

        __nv_bfloat16* A0 = sm2 + buf * G2_BUF_ELEMS;
        __nv_bfloat16* B0 = A0 + 2 * G2_A_SZ;
#pragma unroll
        for (int kk = 0; kk < 2; kk++) {
            const int k0 = kk * 16;
#pragma unroll
            for (int p = 0; p < 3; p++) {           // (hi,hi), (hi,lo), (lo,hi)
                const int pa = (p == 2) ? 1 : 0;
                const int pb = (p == 1) ? 1 : 0;
                wmma::fragment<wmma::matrix_a, 16, 16, 16, __nv_bfloat16, wmma::row_major> af[4];
                wmma::fragment<wmma::matrix_b, 16, 16, 16, __nv_bfloat16, wmma::col_major> bf[4];
#pragma unroll
                for (int mi = 0; mi < 4; mi++)
                    wmma::load_matrix_sync(af[mi],
                        A0 + pa * G2_A_SZ + (warp_m * 64 + mi * 16) * G2_LD + k0, G2_LD);
#pragma unroll
                for (int ni = 0; ni < 4; ni++)
                    wmma::load_matrix_sync(bf[ni],
                        B0 + pb * G2_B_SZ + (warp_n * 64 + ni * 16) * G2_LD + k0, G2_LD);
#pragma unroll
                for (int mi = 0; mi < 4; mi++)
#pragma unroll
                    for (int ni = 0; ni < 4; ni++)
                        wmma::mma_sync(acc[mi][ni], af[mi], bf[ni], acc[mi][ni]);
            }
        }
        __syncthreads();                 // all warps done reading buf
        if (c + 2 < 16)
            issue_chunk(buf, (c + 2) * 32);   // refill freed buffer
    }

#pragma unroll
    for (int mi = 0; mi < 4; mi++)
#pragma unroll
        for (int ni = 0; ni < 4; ni++) {
            int m = arow + warp_m * 64 + mi * 16;           // < 512 (C padded)
            int n = brow + warp_n * 64 + ni * 16;           // < 32000
            wmma::store_matrix_sync(C + (size_t)m * VV + n, acc[mi][ni], VV,
                                    wmma::mem_row_major);
        }
}

// ---------------- fused single-pass row softmax over V=32000 ----------------
__global__ void __launch_bounds__(512)
softmax_kernel(float* __restrict__ out)
{
    extern __shared__ float buf[];                     // 32000 floats
    __shared__ float red[512];
    const int t = blockIdx.x;
    const int tid = threadIdx.x;
    const float4* r4 = (const float4*)(g_logits + (size_t)t * VV);
    float4* b4 = (float4*)buf;
    float4* o4 = (float4*)(out + (size_t)t * VV);

    float mx = -3.402823466e38f;
    for (int i = tid; i < VV / 4; i += 512) {
        float4 v = r4[i];
        b4[i] = v;
        mx = fmaxf(mx, fmaxf(fmaxf(v.x, v.y), fmaxf(v.z, v.w)));
    }
    red[tid] = mx; __syncthreads();
    for (int o = 256; o > 0; o >>= 1) {
        if (tid < o) red[tid] = fmaxf(red[tid], red[tid + o]);
        __syncthreads();
    }
    mx = red[0]; __syncthreads();

    float sum = 0.f;
    for (int i = tid; i < VV / 4; i += 512) {
        float4 v = b4[i];
        v.x = __expf(v.x - mx); v.y = __expf(v.y - mx);
        v.z = __expf(v.z - mx); v.w = __expf(v.w - mx);
        b4[i] = v;
        sum += (v.x + v.y) + (v.z + v.w);
    }
    red[tid] = sum; __syncthreads();
    for (int o = 256; o > 0; o >>= 1) {
        if (tid < o) red[tid] += red[tid + o];
        __syncthreads();
    }
    float inv = 1.f / red[0];

    for (int i = tid; i < VV / 4; i += 512) {
        float4 v = b4[i];
        v.x *= inv; v.y *= inv; v.z *= inv; v.w *= inv;
        o4[i] = v;
    }
}

// ---------------- launch ----------------
extern "C" void kernel_launch(void* const* d_in, const int* in_sizes, int n_in,
                              void* d_out, int out_size)
{
    const float* sent = (const float*)d_in[0];
    const float* W_e  = (const float*)d_in[1];
    const float* W_x  = (const float*)d_in[2];
    const float* W_h  = (const float*)d_in[3];
    const float* W_p  = (const float*)d_in[4];
    const float* b    = (const float*)d_in[5];
    float* out = (float*)d_out;

    float *part, *logits;
    cudaGetSymbolAddress((void**)&part,   g_part);
    cudaGetSymbolAddress((void**)&logits, g_logits);

    cudaFuncSetAttribute(softmax_kernel,
                         cudaFuncAttributeMaxDynamicSharedMemorySize, VV * 4);
    cudaFuncSetAttribute(gemm2_wmma,
                         cudaFuncAttributeMaxDynamicSharedMemorySize, G2_SMEM);

    // W_p hi/lo split (independent of everything else)
    prep_wp_kernel<<<(VV * 512 + 1023) / 1024, 1024>>>(W_p);
    // emb partials: sent[0:511] @ W_e^T, split-K=25
    gemm_nt128<<<dim3(4, 4, SPLITS), 256>>>(sent, VV, W_e, VV,
                                            part, 512, (size_t)512 * 512, TT, KCHUNK);
    reduce_emb_kernel<<<(TT * EE + 255) / 256, 256>>>();
    xproj_kernel<<<dim3(8, 8), 256>>>(W_x, b);
    rnn_kernel<<<8, 1024>>>(W_h);
    prep_hs_kernel<<<(512 * 512 + 1023) / 1024, 1024>>>();
    // logits = hs @ W_p^T on tensor cores (WMMA bf16 3-pass, cp.async pipeline)
    gemm2_wmma<<<dim3(125, 4), 256, G2_SMEM>>>(logits);
    softmax_kernel<<<TT, 512, VV * 4>>>(out);
}

// round 12
// speedup vs baseline: 1.1167x; 1.1167x over previous
#include <cuda_runtime.h>
#include <cuda_bf16.h>
#include <mma.h>
#include <cstdint>
#include <cstddef>

using namespace nvcuda;

#define TT 511          // T-1 rows
#define VV 32000
#define EE 512
#define HH 512
#define SPLITS1 40      // split-K factor for GEMM1 (K=32000 -> 800 per split)
#define KSPLIT1 800

// ---------------- scratch (__device__ globals; no allocation) ----------------
__device__ float g_part[SPLITS1 * 512 * 512];
__device__ float g_emb[TT * EE];
__device__ float g_xproj[TT * HH];
__device__ float g_hs[TT * HH];
__device__ float g_logits[(size_t)512 * VV];     // padded to 512 rows for wmma store
__device__ __nv_bfloat16 g_wp_h[(size_t)VV * 512];
__device__ __nv_bfloat16 g_wp_l[(size_t)VV * 512];
__device__ __nv_bfloat16 g_hs_h[512 * 512];      // padded to 512 rows (zeros)
__device__ __nv_bfloat16 g_hs_l[512 * 512];
__device__ __nv_bfloat16 g_sent_h[(size_t)512 * VV];  // sent padded to 512 rows
__device__ __nv_bfloat16 g_sent_l[(size_t)512 * VV];
__device__ __nv_bfloat16 g_we_h[(size_t)512 * VV];    // W_e [512, 32000]
__device__ __nv_bfloat16 g_we_l[(size_t)512 * VV];

// ---------------- f32x2 helpers (rnn) ----------------
__device__ __forceinline__ void fma2(unsigned long long& d, unsigned long long a,
                                     unsigned long long b) {
    asm("fma.rn.f32x2 %0, %1, %2, %0;" : "+l"(d) : "l"(a), "l"(b));
}
__device__ __forceinline__ float2 unpack2(unsigned long long d) {
    float2 r;
    asm("mov.b64 {%0, %1}, %2;" : "=f"(r.x), "=f"(r.y) : "l"(d));
    return r;
}

// ---------------- reduce split-K partials into emb ----------------
__global__ void reduce_emb_kernel()
{
    int i = blockIdx.x * 256 + threadIdx.x;
    if (i >= TT * EE) return;
    float s = 0.f;
#pragma unroll
    for (int p = 0; p < SPLITS1; p++) s += g_part[p * (512 * 512) + i];
    g_emb[i] = s;
}

// ---------------- xproj = emb @ W_x^T + b ----------------
__global__ void __launch_bounds__(256)
xproj_kernel(const float* __restrict__ W_x, const float* __restrict__ bias)
{
    __shared__ float As[16][68];
    __shared__ float Bs[16][68];
    const int tid = threadIdx.x;
    const int nt = blockIdx.x, mt = blockIdx.y;
    const int ty = tid >> 4, tx = tid & 15;
    const int m0 = ty * 4, n0 = tx * 4;
    float acc[4][4] = {};

    for (int kb = 0; kb < 512; kb += 16) {
        int m = tid >> 2, k4 = (tid & 3) << 2;
        float4 va = make_float4(0.f, 0.f, 0.f, 0.f);
        int ra = mt * 64 + m;
        if (ra < TT) va = *(const float4*)(g_emb + (size_t)ra * 512 + kb + k4);
        As[k4 + 0][m] = va.x; As[k4 + 1][m] = va.y;
        As[k4 + 2][m] = va.z; As[k4 + 3][m] = va.w;
        float4 vb = *(const float4*)(W_x + (size_t)(nt * 64 + m) * 512 + kb + k4);
        Bs[k4 + 0][m] = vb.x; Bs[k4 + 1][m] = vb.y;
        Bs[k4 + 2][m] = vb.z; Bs[k4 + 3][m] = vb.w;
        __syncthreads();
#pragma unroll
        for (int k = 0; k < 16; k++) {
            float4 a = *(const float4*)&As[k][m0];
            float4 b = *(const float4*)&Bs[k][n0];
            float aa[4] = {a.x, a.y, a.z, a.w};
            float bb[4] = {b.x, b.y, b.z, b.w};
#pragma unroll
            for (int i = 0; i < 4; i++)
#pragma unroll
                for (int j = 0; j < 4; j++) acc[i][j] += aa[i] * bb[j];
        }
        __syncthreads();
    }
#pragma unroll
    for (int i = 0; i < 4; i++) {
        int r = mt * 64 + m0 + i;
        if (r >= TT) continue;
#pragma unroll
        for (int j = 0; j < 4; j++) {
            int col = nt * 64 + n0 + j;
            g_xproj[(size_t)r * 512 + col] = acc[i][j] + bias[col];
        }
    }
}

// ---------------- Elman recurrence: EXACT R1 version (measured ~621us) ----------
__global__ void __cluster_dims__(8, 1, 1) __launch_bounds__(1024, 1)
rnn_kernel(const float* __restrict__ W_h)
{
    __shared__ float hbuf[2][512];
    __shared__ float pbuf[64][17];
    const int tid = threadIdx.x;
    const int w = tid >> 5, l = tid & 31;
    const int g = w & 1, s = w >> 1;
    const int c = (int)blockIdx.x;
    const int row = c * 64 + g * 32 + l;
    const int kbase = s * 32;

    ulonglong2 wv[8];
    {
        const ulonglong2* wp = (const ulonglong2*)(W_h + (size_t)row * 512 + kbase);
#pragma unroll
        for (int j = 0; j < 8; j++) wv[j] = wp[j];
    }
    for (int i = tid; i < 512; i += 1024) hbuf[0][i] = 0.f;

    uint32_t hbase_local = (uint32_t)__cvta_generic_to_shared(&hbuf[0][0]);
    uint32_t peer[8];
#pragma unroll
    for (int p = 0; p < 8; p++)
        asm("mapa.shared::cluster.u32 %0, %1, %2;" : "=r"(peer[p]) : "r"(hbase_local), "r"(p));

    float xp = (tid < 64) ? g_xproj[(size_t)c * 64 + tid] : 0.f;

    __syncthreads();
    asm volatile("barrier.cluster.arrive.aligned;" ::: "memory");
    asm volatile("barrier.cluster.wait.aligned;" ::: "memory");

    for (int t = 0; t < TT; t++) {
        const int cur = t & 1;
        const ulonglong2* hp = (const ulonglong2*)&hbuf[cur][kbase];
        unsigned long long acc = 0ull;
#pragma unroll
        for (int j = 0; j < 8; j++) {
            ulonglong2 hh = hp[j];
            fma2(acc, wv[j].x, hh.x);
            fma2(acc, wv[j].y, hh.y);
        }
        float2 f = unpack2(acc);
        pbuf[g * 32 + l][s] = f.x + f.y;
        __syncthreads();
        if (tid < 64) {
            float x = xp;
#pragma unroll
            for (int s2 = 0; s2 < 16; s2++) x += pbuf[tid][s2];
            float h = 1.f / (1.f + __expf(-x));
            g_hs[(size_t)t * 512 + c * 64 + tid] = h;
            uint32_t off = (uint32_t)(((cur ^ 1) * 512 + c * 64 + tid) * 4);
#pragma unroll
            for (int p = 0; p < 8; p++)
                asm volatile("st.shared::cluster.f32 [%0], %1;"
                             :: "r"(peer[p] + off), "f"(h) : "memory");
            int tn = (t + 1 < TT) ? (t + 1) : t;
            xp = g_xproj[(size_t)tn * 512 + c * 64 + tid];
        }
        asm volatile("barrier.cluster.arrive.aligned;" ::: "memory");
        asm volatile("barrier.cluster.wait.aligned;" ::: "memory");
    }
}

// ---------------- bf16 hi/lo split preps ----------------
__global__ void prep_wp_kernel(const float* __restrict__ W_p)
{
    size_t i = (size_t)blockIdx.x * 1024 + threadIdx.x;
    if (i >= (size_t)VV * 512) return;
    float v = W_p[i];
    __nv_bfloat16 h = __float2bfloat16_rn(v);
    g_wp_h[i] = h;
    g_wp_l[i] = __float2bfloat16_rn(v - __bfloat162float(h));
}
__global__ void prep_hs_kernel()
{
    int i = blockIdx.x * 1024 + threadIdx.x;
    if (i >= 512 * 512) return;
    float v = (i < TT * 512) ? g_hs[i] : 0.f;
    __nv_bfloat16 h = __float2bfloat16_rn(v);
    g_hs_h[i] = h;
    g_hs_l[i] = __float2bfloat16_rn(v - __bfloat162float(h));
}
__global__ void prep_sent_kernel(const float* __restrict__ sent)
{
    size_t i = (size_t)blockIdx.x * 1024 + threadIdx.x;
    if (i >= (size_t)512 * VV) return;
    float v = (i < (size_t)TT * VV) ? sent[i] : 0.f;   // pad row 511 with zeros
    __nv_bfloat16 h = __float2bfloat16_rn(v);
    g_sent_h[i] = h;
    g_sent_l[i] = __float2bfloat16_rn(v - __bfloat162float(h));
}
__global__ void prep_we_kernel(const float* __restrict__ W_e)
{
    size_t i = (size_t)blockIdx.x * 1024 + threadIdx.x;
    if (i >= (size_t)512 * VV) return;
    float v = W_e[i];
    __nv_bfloat16 h = __float2bfloat16_rn(v);
    g_we_h[i] = h;
    g_we_l[i] = __float2bfloat16_rn(v - __bfloat162float(h));
}

// ---------------- generic WMMA bf16 3-pass GEMM (C += split over z) --------------
// C[m,n] = sum_k A[m,k]*B[n,k], both K-major. A,B given as hi/lo bf16 splits.
// CTA tile 128(M) x 256(N), 8 warps 2x4, warp tile 64x64 (4x4 m16n16k16 frags).
// 3 passes (hh, hl, lh). K chunks of 32, depth-2 cp.async pipeline.
// Split-K via blockIdx.z: kOff = z*kPerSplit, output at C + z*zStride.
// A rows must be padded to mt*128+128; B rows to nt*256+256.
#define G2_LD 48
#define G2_A_SZ (128 * G2_LD)
#define G2_B_SZ (256 * G2_LD)
#define G2_BUF_ELEMS (2 * G2_A_SZ + 2 * G2_B_SZ)     // 36864 elems = 73728 B
#define G2_SMEM (2 * G2_BUF_ELEMS * 2)               // 147456 bytes

__device__ __forceinline__ void cp_async16(uint32_t dst, const void* src) {
    asm volatile("cp.async.cg.shared.global [%0], [%1], 16;"
                 :: "r"(dst), "l"(src));
}

__global__ void __launch_bounds__(256, 1)
gemm_wmma3(const __nv_bfloat16* __restrict__ Ah_g, const __nv_bfloat16* __restrict__ Al_g,
           int lda,
           const __nv_bfloat16* __restrict__ Bh_g, const __nv_bfloat16* __restrict__ Bl_g,
           int ldb,
           float* __restrict__ C, int ldc, size_t zStride, int kPerSplit)
{
    extern __shared__ __align__(32) __nv_bfloat16 sm2[];
    const uint32_t sbase = (uint32_t)__cvta_generic_to_shared(sm2);
    const __nv_bfloat16* Agm[2] = { Ah_g, Al_g };
    const __nv_bfloat16* Bgm[2] = { Bh_g, Bl_g };

    const int tid = threadIdx.x;
    const int wid = tid >> 5;
    const int warp_m = wid >> 2;          // 0..1
    const int warp_n = wid & 3;           // 0..3
    const int nt = blockIdx.x, mt = blockIdx.y, sz = blockIdx.z;
    const int arow = mt * 128, brow = nt * 256;
    const int kOff = sz * kPerSplit;
    const int nChunks = kPerSplit >> 5;
    float* Cz = C + (size_t)sz * zStride;

    // per-thread load geometry (fixed): A 4 items, B 8 items of 16B
    int a_off[4];
    const __nv_bfloat16* a_src[4];
#pragma unroll
    for (int i = 0; i < 4; i++) {
        int lin = tid + i * 256;
        int s = lin >> 9, rem = lin & 511;
        int r = rem >> 2, seg = rem & 3;
        a_off[i] = s * G2_A_SZ + r * G2_LD + seg * 8;
        a_src[i] = Agm[s] + (size_t)(arow + r) * lda + kOff + seg * 8;
    }
    int b_off[8];
    const __nv_bfloat16* b_src[8];
#pragma unroll
    for (int i = 0; i < 8; i++) {
        int lin = tid + i * 256;
        int s = lin >> 10, rem = lin & 1023;
        int r = rem >> 2, seg = rem & 3;
        b_off[i] = 2 * G2_A_SZ + s * G2_B_SZ + r * G2_LD + seg * 8;
        b_src[i] = Bgm[s] + (size_t)(brow + r) * ldb + kOff + seg * 8;
    }

    auto issue_chunk = [&](int buf, int kc) {
        uint32_t base = sbase + (uint32_t)(buf * G2_BUF_ELEMS) * 2;
#pragma unroll
        for (int i = 0; i < 4; i++)
            cp_async16(base + (uint32_t)a_off[i] * 2, a_src[i] + kc);
#pragma unroll
        for (int i = 0; i < 8; i++)
            cp_async16(base + (uint32_t)b_off[i] * 2, b_src[i] + kc);
        asm volatile("cp.async.commit_group;" ::: "memory");
    };

    wmma::fragment<wmma::accumulator, 16, 16, 16, float> acc[4][4];
#pragma unroll
    for (int mi = 0; mi < 4; mi++)
#pragma unroll
        for (int ni = 0; ni < 4; ni++) wmma::fill_fragment(acc[mi][ni], 0.f);

    // prologue: chunks 0 and 1 in flight
    issue_chunk(0, 0);
    if (nChunks > 1) issue_chunk(1, 32);

    for (int c = 0; c < nChunks; c++) {
        const int buf = c & 1;
        if (c + 2 < nChunks)
            asm volatile("cp.async.wait_group 1;" ::: "memory");
        else
            asm volatile("cp.async.wait_group 0;" ::: "memory");
        __syncthreads();                 // chunk c's data visible to all warps

        __nv_bfloat16* A0 = sm2 + buf * G2_BUF_ELEMS;
        __nv_bfloat16* B0 = A0 + 2 * G2_A_SZ;
#pragma unroll
        for (int kk = 0; kk < 2; kk++) {
            const int k0 = kk * 16;
#pragma unroll
            for (int p = 0; p < 3; p++) {           // (hi,hi), (hi,lo), (lo,hi)
                const int pa = (p == 2) ? 1 : 0;
                const int pb = (p == 1) ? 1 : 0;
                wmma::fragment<wmma::matrix_a, 16, 16, 16, __nv_bfloat16, wmma::row_major> af[4];
                wmma::fragment<wmma::matrix_b, 16, 16, 16, __nv_bfloat16, wmma::col_major> bf[4];
#pragma unroll
                for (int mi = 0; mi < 4; mi++)
                    wmma::load_matrix_sync(af[mi],
                        A0 + pa * G2_A_SZ + (warp_m * 64 + mi * 16) * G2_LD + k0, G2_LD);
#pragma unroll
                for (int ni = 0; ni < 4; ni++)
                    wmma::load_matrix_sync(bf[ni],
                        B0 + pb * G2_B_SZ + (warp_n * 64 + ni * 16) * G2_LD + k0, G2_LD);
#pragma unroll
                for (int mi = 0; mi < 4; mi++)
#pragma unroll
                    for (int ni = 0; ni < 4; ni++)
                        wmma::mma_sync(acc[mi][ni], af[mi], bf[ni], acc[mi][ni]);
            }
        }
        __syncthreads();                 // all warps done reading buf
        if (c + 2 < nChunks)
            issue_chunk(buf, (c + 2) * 32);   // refill freed buffer
    }

#pragma unroll
    for (int mi = 0; mi < 4; mi++)
#pragma unroll
        for (int ni = 0; ni < 4; ni++) {
            int m = arow + warp_m * 64 + mi * 16;
            int n = brow + warp_n * 64 + ni * 16;
            wmma::store_matrix_sync(Cz + (size_t)m * ldc + n, acc[mi][ni], ldc,
                                    wmma::mem_row_major);
        }
}

// ---------------- fused single-pass row softmax over V=32000 ----------------
__global__ void __launch_bounds__(512)
softmax_kernel(float* __restrict__ out)
{
    extern __shared__ float buf[];                     // 32000 floats
    __shared__ float red[512];
    const int t = blockIdx.x;
    const int tid = threadIdx.x;
    const float4* r4 = (const float4*)(g_logits + (size_t)t * VV);
    float4* b4 = (float4*)buf;
    float4* o4 = (float4*)(out + (size_t)t * VV);

    float mx = -3.402823466e38f;
    for (int i = tid; i < VV / 4; i += 512) {
        float4 v = r4[i];
        b4[i] = v;
        mx = fmaxf(mx, fmaxf(fmaxf(v.x, v.y), fmaxf(v.z, v.w)));
    }
    red[tid] = mx; __syncthreads();
    for (int o = 256; o > 0; o >>= 1) {
        if (tid < o) red[tid] = fmaxf(red[tid], red[tid + o]);
        __syncthreads();
    }
    mx = red[0]; __syncthreads();

    float sum = 0.f;
    for (int i = tid; i < VV / 4; i += 512) {
        float4 v = b4[i];
        v.x = __expf(v.x - mx); v.y = __expf(v.y - mx);
        v.z = __expf(v.z - mx); v.w = __expf(v.w - mx);
        b4[i] = v;
        sum += (v.x + v.y) + (v.z + v.w);
    }
    red[tid] = sum; __syncthreads();
    for (int o = 256; o > 0; o >>= 1) {
        if (tid < o) red[tid] += red[tid + o];
        __syncthreads();
    }
    float inv = 1.f / red[0];

    for (int i = tid; i < VV / 4; i += 512) {
        float4 v = b4[i];
        v.x *= inv; v.y *= inv; v.z *= inv; v.w *= inv;
        o4[i] = v;
    }
}

// ---------------- launch ----------------
extern "C" void kernel_launch(void* const* d_in, const int* in_sizes, int n_in,
                              void* d_out, int out_size)
{
    const float* sent = (const float*)d_in[0];
    const float* W_e  = (const float*)d_in[1];
    const float* W_x  = (const float*)d_in[2];
    const float* W_h  = (const float*)d_in[3];
    const float* W_p  = (const float*)d_in[4];
    const float* b    = (const float*)d_in[5];
    float* out = (float*)d_out;

    float *part, *logits;
    __nv_bfloat16 *sh, *sl, *wh, *wl, *hh, *hl, *ph, *pl;
    cudaGetSymbolAddress((void**)&part,   g_part);
    cudaGetSymbolAddress((void**)&logits, g_logits);
    cudaGetSymbolAddress((void**)&sh, g_sent_h);
    cudaGetSymbolAddress((void**)&sl, g_sent_l);
    cudaGetSymbolAddress((void**)&wh, g_we_h);
    cudaGetSymbolAddress((void**)&wl, g_we_l);
    cudaGetSymbolAddress((void**)&hh, g_hs_h);
    cudaGetSymbolAddress((void**)&hl, g_hs_l);
    cudaGetSymbolAddress((void**)&ph, g_wp_h);
    cudaGetSymbolAddress((void**)&pl, g_wp_l);

    cudaFuncSetAttribute(softmax_kernel,
                         cudaFuncAttributeMaxDynamicSharedMemorySize, VV * 4);
    cudaFuncSetAttribute(gemm_wmma3,
                         cudaFuncAttributeMaxDynamicSharedMemorySize, G2_SMEM);

    const int nPrep = (512 * VV + 1023) / 1024;
    // splits for GEMM1 inputs + W_p (all independent)
    prep_sent_kernel<<<nPrep, 1024>>>(sent);
    prep_we_kernel<<<nPrep, 1024>>>(W_e);
    prep_wp_kernel<<<nPrep, 1024>>>(W_p);
    // emb partials = sent @ W_e^T  (WMMA 3-pass, split-K=40, 800 k per split)
    gemm_wmma3<<<dim3(2, 4, SPLITS1), 256, G2_SMEM>>>(
        sh, sl, VV, wh, wl, VV, part, 512, (size_t)512 * 512, KSPLIT1);
    reduce_emb_kernel<<<(TT * EE + 255) / 256, 256>>>();
    xproj_kernel<<<dim3(8, 8), 256>>>(W_x, b);
    rnn_kernel<<<8, 1024>>>(W_h);
    prep_hs_kernel<<<(512 * 512 + 1023) / 1024, 1024>>>();
    // logits = hs @ W_p^T  (WMMA 3-pass, no split-K)
    gemm_wmma3<<<dim3(125, 4, 1), 256, G2_SMEM>>>(
        hh, hl, 512, ph, pl, 512, logits, VV, 0, 512);
    softmax_kernel<<<TT, 512, VV * 4>>>(out);
}

// round 13
// speedup vs baseline: 1.1795x; 1.0562x over previous
#include <cuda_runtime.h>
#include <cuda_bf16.h>
#include <mma.h>
#include <cstdint>
#include <cstddef>

using namespace nvcuda;

#define TT 511          // T-1 rows
#define VV 32000
#define EE 512
#define HH 512
#define SPLITS1 40      // split-K factor for GEMM1 (K=32000 -> 800 per split)
#define KSPLIT1 800

// ---------------- scratch (__device__ globals; no allocation) ----------------
__device__ float g_part[SPLITS1 * 512 * 512];
__device__ float g_emb[TT * EE];
__device__ float g_xproj[TT * HH];
__device__ float g_hs[TT * HH];
__device__ float g_logits[(size_t)512 * VV];     // padded to 512 rows for wmma store
__device__ __nv_bfloat16 g_wp_h[(size_t)VV * 512];
__device__ __nv_bfloat16 g_wp_l[(size_t)VV * 512];
__device__ __nv_bfloat16 g_hs_h[512 * 512];      // padded to 512 rows (zeros)
__device__ __nv_bfloat16 g_hs_l[512 * 512];
__device__ __nv_bfloat16 g_sent_h[(size_t)512 * VV];  // sent padded to 512 rows
__device__ __nv_bfloat16 g_sent_l[(size_t)512 * VV];
__device__ __nv_bfloat16 g_we_h[(size_t)512 * VV];    // W_e [512, 32000]
__device__ __nv_bfloat16 g_we_l[(size_t)512 * VV];

// ---------------- f32x2 helpers (rnn) ----------------
__device__ __forceinline__ void fma2(unsigned long long& d, unsigned long long a,
                                     unsigned long long b) {
    asm("fma.rn.f32x2 %0, %1, %2, %0;" : "+l"(d) : "l"(a), "l"(b));
}
__device__ __forceinline__ float2 unpack2(unsigned long long d) {
    float2 r;
    asm("mov.b64 {%0, %1}, %2;" : "=f"(r.x), "=f"(r.y) : "l"(d));
    return r;
}

// ---------------- reduce split-K partials into emb ----------------
__global__ void reduce_emb_kernel()
{
    int i = blockIdx.x * 256 + threadIdx.x;
    if (i >= TT * EE) return;
    float s = 0.f;
#pragma unroll
    for (int p = 0; p < SPLITS1; p++) s += g_part[p * (512 * 512) + i];
    g_emb[i] = s;
}

// ---------------- xproj = emb @ W_x^T + b ----------------
__global__ void __launch_bounds__(256)
xproj_kernel(const float* __restrict__ W_x, const float* __restrict__ bias)
{
    __shared__ float As[16][68];
    __shared__ float Bs[16][68];
    const int tid = threadIdx.x;
    const int nt = blockIdx.x, mt = blockIdx.y;
    const int ty = tid >> 4, tx = tid & 15;
    const int m0 = ty * 4, n0 = tx * 4;
    float acc[4][4] = {};

    for (int kb = 0; kb < 512; kb += 16) {
        int m = tid >> 2, k4 = (tid & 3) << 2;
        float4 va = make_float4(0.f, 0.f, 0.f, 0.f);
        int ra = mt * 64 + m;
        if (ra < TT) va = *(const float4*)(g_emb + (size_t)ra * 512 + kb + k4);
        As[k4 + 0][m] = va.x; As[k4 + 1][m] = va.y;
        As[k4 + 2][m] = va.z; As[k4 + 3][m] = va.w;
        float4 vb = *(const float4*)(W_x + (size_t)(nt * 64 + m) * 512 + kb + k4);
        Bs[k4 + 0][m] = vb.x; Bs[k4 + 1][m] = vb.y;
        Bs[k4 + 2][m] = vb.z; Bs[k4 + 3][m] = vb.w;
        __syncthreads();
#pragma unroll
        for (int k = 0; k < 16; k++) {
            float4 a = *(const float4*)&As[k][m0];
            float4 b = *(const float4*)&Bs[k][n0];
            float aa[4] = {a.x, a.y, a.z, a.w};
            float bb[4] = {b.x, b.y, b.z, b.w};
#pragma unroll
            for (int i = 0; i < 4; i++)
#pragma unroll
                for (int j = 0; j < 4; j++) acc[i][j] += aa[i] * bb[j];
        }
        __syncthreads();
    }
#pragma unroll
    for (int i = 0; i < 4; i++) {
        int r = mt * 64 + m0 + i;
        if (r >= TT) continue;
#pragma unroll
        for (int j = 0; j < 4; j++) {
            int col = nt * 64 + n0 + j;
            g_xproj[(size_t)r * 512 + col] = acc[i][j] + bias[col];
        }
    }
}

// ---------------- Elman recurrence: EXACT R1 version (measured ~621us) ----------
__global__ void __cluster_dims__(8, 1, 1) __launch_bounds__(1024, 1)
rnn_kernel(const float* __restrict__ W_h)
{
    __shared__ float hbuf[2][512];
    __shared__ float pbuf[64][17];
    const int tid = threadIdx.x;
    const int w = tid >> 5, l = tid & 31;
    const int g = w & 1, s = w >> 1;
    const int c = (int)blockIdx.x;
    const int row = c * 64 + g * 32 + l;
    const int kbase = s * 32;

    ulonglong2 wv[8];
    {
        const ulonglong2* wp = (const ulonglong2*)(W_h + (size_t)row * 512 + kbase);
#pragma unroll
        for (int j = 0; j < 8; j++) wv[j] = wp[j];
    }
    for (int i = tid; i < 512; i += 1024) hbuf[0][i] = 0.f;

    uint32_t hbase_local = (uint32_t)__cvta_generic_to_shared(&hbuf[0][0]);
    uint32_t peer[8];
#pragma unroll
    for (int p = 0; p < 8; p++)
        asm("mapa.shared::cluster.u32 %0, %1, %2;" : "=r"(peer[p]) : "r"(hbase_local), "r"(p));

    float xp = (tid < 64) ? g_xproj[(size_t)c * 64 + tid] : 0.f;

    __syncthreads();
    asm volatile("barrier.cluster.arrive.aligned;" ::: "memory");
    asm volatile("barrier.cluster.wait.aligned;" ::: "memory");

    for (int t = 0; t < TT; t++) {
        const int cur = t & 1;
        const ulonglong2* hp = (const ulonglong2*)&hbuf[cur][kbase];
        unsigned long long acc = 0ull;
#pragma unroll
        for (int j = 0; j < 8; j++) {
            ulonglong2 hh = hp[j];
            fma2(acc, wv[j].x, hh.x);
            fma2(acc, wv[j].y, hh.y);
        }
        float2 f = unpack2(acc);
        pbuf[g * 32 + l][s] = f.x + f.y;
        __syncthreads();
        if (tid < 64) {
            float x = xp;
#pragma unroll
            for (int s2 = 0; s2 < 16; s2++) x += pbuf[tid][s2];
            float h = 1.f / (1.f + __expf(-x));
            g_hs[(size_t)t * 512 + c * 64 + tid] = h;
            uint32_t off = (uint32_t)(((cur ^ 1) * 512 + c * 64 + tid) * 4);
#pragma unroll
            for (int p = 0; p < 8; p++)
                asm volatile("st.shared::cluster.f32 [%0], %1;"
                             :: "r"(peer[p] + off), "f"(h) : "memory");
            int tn = (t + 1 < TT) ? (t + 1) : t;
            xp = g_xproj[(size_t)tn * 512 + c * 64 + tid];
        }
        asm volatile("barrier.cluster.arrive.aligned;" ::: "memory");
        asm volatile("barrier.cluster.wait.aligned;" ::: "memory");
    }
}

// ---------------- bf16 hi/lo split preps ----------------
__global__ void prep_wp_kernel(const float* __restrict__ W_p)
{
    size_t i = (size_t)blockIdx.x * 1024 + threadIdx.x;
    if (i >= (size_t)VV * 512) return;
    float v = W_p[i];
    __nv_bfloat16 h = __float2bfloat16_rn(v);
    g_wp_h[i] = h;
    g_wp_l[i] = __float2bfloat16_rn(v - __bfloat162float(h));
}
__global__ void prep_hs_kernel()
{
    int i = blockIdx.x * 1024 + threadIdx.x;
    if (i >= 512 * 512) return;
    float v = (i < TT * 512) ? g_hs[i] : 0.f;
    __nv_bfloat16 h = __float2bfloat16_rn(v);
    g_hs_h[i] = h;
    g_hs_l[i] = __float2bfloat16_rn(v - __bfloat162float(h));
}
__global__ void prep_sent_kernel(const float* __restrict__ sent)
{
    size_t i = (size_t)blockIdx.x * 1024 + threadIdx.x;
    if (i >= (size_t)512 * VV) return;
    float v = (i < (size_t)TT * VV) ? sent[i] : 0.f;   // pad row 511 with zeros
    __nv_bfloat16 h = __float2bfloat16_rn(v);
    g_sent_h[i] = h;
    g_sent_l[i] = __float2bfloat16_rn(v - __bfloat162float(h));
}
__global__ void prep_we_kernel(const float* __restrict__ W_e)
{
    size_t i = (size_t)blockIdx.x * 1024 + threadIdx.x;
    if (i >= (size_t)512 * VV) return;
    float v = W_e[i];
    __nv_bfloat16 h = __float2bfloat16_rn(v);
    g_we_h[i] = h;
    g_we_l[i] = __float2bfloat16_rn(v - __bfloat162float(h));
}

// ---------------- generic WMMA bf16 3-pass GEMM, occ 2 --------------------------
// C[m,n] = sum_k A[m,k]*B[n,k], both K-major, hi/lo bf16 splits, 3 passes.
// CTA tile 128(M) x 128(N), 8 warps 2x4, warp tile 64x32 (4x2 m16n16k16 frags).
// K chunks of 32, depth-2 cp.async pipeline. Smem 2 x 49152 B -> 2 CTAs/SM;
// acc 64 regs + frags ~40 -> no spills. Split-K via blockIdx.z.
#define G2_LD 48
#define G2_A_SZ (128 * G2_LD)                        // elems per split (A or B)
#define G2_BUF_ELEMS (4 * G2_A_SZ)                   // Ah,Al,Bh,Bl = 24576 elems
#define G2_SMEM (2 * G2_BUF_ELEMS * 2)               // 98304 bytes

__device__ __forceinline__ void cp_async16(uint32_t dst, const void* src) {
    asm volatile("cp.async.cg.shared.global [%0], [%1], 16;"
                 :: "r"(dst), "l"(src));
}

__global__ void __launch_bounds__(256, 2)
gemm_wmma3(const __nv_bfloat16* __restrict__ Ah_g, const __nv_bfloat16* __restrict__ Al_g,
           int lda,
           const __nv_bfloat16* __restrict__ Bh_g, const __nv_bfloat16* __restrict__ Bl_g,
           int ldb,
           float* __restrict__ C, int ldc, size_t zStride, int kPerSplit)
{
    extern __shared__ __align__(32) __nv_bfloat16 sm2[];
    const uint32_t sbase = (uint32_t)__cvta_generic_to_shared(sm2);
    const __nv_bfloat16* Agm[2] = { Ah_g, Al_g };
    const __nv_bfloat16* Bgm[2] = { Bh_g, Bl_g };

    const int tid = threadIdx.x;
    const int wid = tid >> 5;
    const int warp_m = wid >> 2;          // 0..1  (64-row halves)
    const int warp_n = wid & 3;           // 0..3  (32-col quarters)
    const int nt = blockIdx.x, mt = blockIdx.y, sz = blockIdx.z;
    const int arow = mt * 128, brow = nt * 128;
    const int kOff = sz * kPerSplit;
    const int nChunks = kPerSplit >> 5;
    float* Cz = C + (size_t)sz * zStride;

    // per-thread load geometry: A and B each 2 splits x 128 rows x 4 x 16B segs
    // = 1024 items / 256 thr = 4 iters each
    int a_off[4], b_off[4];
    const __nv_bfloat16* a_src[4];
    const __nv_bfloat16* b_src[4];
#pragma unroll
    for (int i = 0; i < 4; i++) {
        int lin = tid + i * 256;
        int s = lin >> 9, rem = lin & 511;
        int r = rem >> 2, seg = rem & 3;
        a_off[i] = s * G2_A_SZ + r * G2_LD + seg * 8;
        a_src[i] = Agm[s] + (size_t)(arow + r) * lda + kOff + seg * 8;
        b_off[i] = (2 + s) * G2_A_SZ + r * G2_LD + seg * 8;
        b_src[i] = Bgm[s] + (size_t)(brow + r) * ldb + kOff + seg * 8;
    }

    auto issue_chunk = [&](int buf, int kc) {
        uint32_t base = sbase + (uint32_t)(buf * G2_BUF_ELEMS) * 2;
#pragma unroll
        for (int i = 0; i < 4; i++) {
            cp_async16(base + (uint32_t)a_off[i] * 2, a_src[i] + kc);
            cp_async16(base + (uint32_t)b_off[i] * 2, b_src[i] + kc);
        }
        asm volatile("cp.async.commit_group;" ::: "memory");
    };

    wmma::fragment<wmma::accumulator, 16, 16, 16, float> acc[4][2];
#pragma unroll
    for (int mi = 0; mi < 4; mi++)
#pragma unroll
        for (int ni = 0; ni < 2; ni++) wmma::fill_fragment(acc[mi][ni], 0.f);

    issue_chunk(0, 0);
    if (nChunks > 1) issue_chunk(1, 32);

    for (int c = 0; c < nChunks; c++) {
        const int buf = c & 1;
        if (c + 2 < nChunks)
            asm volatile("cp.async.wait_group 1;" ::: "memory");
        else
            asm volatile("cp.async.wait_group 0;" ::: "memory");
        __syncthreads();

        __nv_bfloat16* A0 = sm2 + buf * G2_BUF_ELEMS;
        __nv_bfloat16* B0 = A0 + 2 * G2_A_SZ;
#pragma unroll
        for (int kk = 0; kk < 2; kk++) {
            const int k0 = kk * 16;
#pragma unroll
            for (int p = 0; p < 3; p++) {           // (hi,hi), (hi,lo), (lo,hi)
                const int pa = (p == 2) ? 1 : 0;
                const int pb = (p == 1) ? 1 : 0;
                wmma::fragment<wmma::matrix_a, 16, 16, 16, __nv_bfloat16, wmma::row_major> af[4];
                wmma::fragment<wmma::matrix_b, 16, 16, 16, __nv_bfloat16, wmma::col_major> bf[2];
#pragma unroll
                for (int mi = 0; mi < 4; mi++)
                    wmma::load_matrix_sync(af[mi],
                        A0 + pa * G2_A_SZ + (warp_m * 64 + mi * 16) * G2_LD + k0, G2_LD);
#pragma unroll
                for (int ni = 0; ni < 2; ni++)
                    wmma::load_matrix_sync(bf[ni],
                        B0 + pb * G2_A_SZ + (warp_n * 32 + ni * 16) * G2_LD + k0, G2_LD);
#pragma unroll
                for (int mi = 0; mi < 4; mi++)
#pragma unroll
                    for (int ni = 0; ni < 2; ni++)
                        wmma::mma_sync(acc[mi][ni], af[mi], bf[ni], acc[mi][ni]);
            }
        }
        __syncthreads();
        if (c + 2 < nChunks)
            issue_chunk(buf, (c + 2) * 32);
    }

#pragma unroll
    for (int mi = 0; mi < 4; mi++)
#pragma unroll
        for (int ni = 0; ni < 2; ni++) {
            int m = arow + warp_m * 64 + mi * 16;
            int n = brow + warp_n * 32 + ni * 16;
            wmma::store_matrix_sync(Cz + (size_t)m * ldc + n, acc[mi][ni], ldc,
                                    wmma::mem_row_major);
        }
}

// ---------------- fused single-pass row softmax over V=32000 ----------------
__global__ void __launch_bounds__(512)
softmax_kernel(float* __restrict__ out)
{
    extern __shared__ float buf[];                     // 32000 floats
    __shared__ float red[512];
    const int t = blockIdx.x;
    const int tid = threadIdx.x;
    const float4* r4 = (const float4*)(g_logits + (size_t)t * VV);
    float4* b4 = (float4*)buf;
    float4* o4 = (float4*)(out + (size_t)t * VV);

    float mx = -3.402823466e38f;
    for (int i = tid; i < VV / 4; i += 512) {
        float4 v = r4[i];
        b4[i] = v;
        mx = fmaxf(mx, fmaxf(fmaxf(v.x, v.y), fmaxf(v.z, v.w)));
    }
    red[tid] = mx; __syncthreads();
    for (int o = 256; o > 0; o >>= 1) {
        if (tid < o) red[tid] = fmaxf(red[tid], red[tid + o]);
        __syncthreads();
    }
    mx = red[0]; __syncthreads();

    float sum = 0.f;
    for (int i = tid; i < VV / 4; i += 512) {
        float4 v = b4[i];
        v.x = __expf(v.x - mx); v.y = __expf(v.y - mx);
        v.z = __expf(v.z - mx); v.w = __expf(v.w - mx);
        b4[i] = v;
        sum += (v.x + v.y) + (v.z + v.w);
    }
    red[tid] = sum; __syncthreads();
    for (int o = 256; o > 0; o >>= 1) {
        if (tid < o) red[tid] += red[tid + o];
        __syncthreads();
    }
    float inv = 1.f / red[0];

    for (int i = tid; i < VV / 4; i += 512) {
        float4 v = b4[i];
        v.x *= inv; v.y *= inv; v.z *= inv; v.w *= inv;
        o4[i] = v;
    }
}

// ---------------- launch ----------------
extern "C" void kernel_launch(void* const* d_in, const int* in_sizes, int n_in,
                              void* d_out, int out_size)
{
    const float* sent = (const float*)d_in[0];
    const float* W_e  = (const float*)d_in[1];
    const float* W_x  = (const float*)d_in[2];
    const float* W_h  = (const float*)d_in[3];
    const float* W_p  = (const float*)d_in[4];
    const float* b    = (const float*)d_in[5];
    float* out = (float*)d_out;

    float *part, *logits;
    __nv_bfloat16 *sh, *sl, *wh, *wl, *hh, *hl, *ph, *pl;
    cudaGetSymbolAddress((void**)&part,   g_part);
    cudaGetSymbolAddress((void**)&logits, g_logits);
    cudaGetSymbolAddress((void**)&sh, g_sent_h);
    cudaGetSymbolAddress((void**)&sl, g_sent_l);
    cudaGetSymbolAddress((void**)&wh, g_we_h);
    cudaGetSymbolAddress((void**)&wl, g_we_l);
    cudaGetSymbolAddress((void**)&hh, g_hs_h);
    cudaGetSymbolAddress((void**)&hl, g_hs_l);
    cudaGetSymbolAddress((void**)&ph, g_wp_h);
    cudaGetSymbolAddress((void**)&pl, g_wp_l);

    cudaFuncSetAttribute(softmax_kernel,
                         cudaFuncAttributeMaxDynamicSharedMemorySize, VV * 4);
    cudaFuncSetAttribute(gemm_wmma3,
                         cudaFuncAttributeMaxDynamicSharedMemorySize, G2_SMEM);

    const int nPrep = (512 * VV + 1023) / 1024;
    prep_sent_kernel<<<nPrep, 1024>>>(sent);
    prep_we_kernel<<<nPrep, 1024>>>(W_e);
    prep_wp_kernel<<<nPrep, 1024>>>(W_p);
    // emb partials = sent @ W_e^T  (WMMA 3-pass, split-K=40, 800 k per split)
    gemm_wmma3<<<dim3(4, 4, SPLITS1), 256, G2_SMEM>>>(
        sh, sl, VV, wh, wl, VV, part, 512, (size_t)512 * 512, KSPLIT1);
    reduce_emb_kernel<<<(TT * EE + 255) / 256, 256>>>();
    xproj_kernel<<<dim3(8, 8), 256>>>(W_x, b);
    rnn_kernel<<<8, 1024>>>(W_h);
    prep_hs_kernel<<<(512 * 512 + 1023) / 1024, 1024>>>();
    // logits = hs @ W_p^T  (WMMA 3-pass, no split-K)
    gemm_wmma3<<<dim3(250, 4, 1), 256, G2_SMEM>>>(
        hh, hl, 512, ph, pl, 512, logits, VV, 0, 512);
    softmax_kernel<<<TT, 512, VV * 4>>>(out);
}

// round 14
// speedup vs baseline: 1.2642x; 1.0718x over previous
#include <cuda_runtime.h>
#include <cuda_bf16.h>
#include <mma.h>
#include <cstdint>
#include <cstddef>

using namespace nvcuda;

#define TT 511          // T-1 rows
#define VV 32000
#define EE 512
#define HH 512
#define SPLITS1 40      // split-K factor for GEMM1 (K=32000 -> 800 per split)
#define KSPLIT1 800

// ---------------- scratch (__device__ globals; no allocation) ----------------
__device__ float g_part[SPLITS1 * 512 * 512];
__device__ float g_emb[TT * EE];
__device__ float g_xproj[TT * HH];
__device__ float g_hs[TT * HH];
__device__ float g_logits[(size_t)512 * VV];     // padded to 512 rows for wmma store
__device__ __nv_bfloat16 g_wp_h[(size_t)VV * 512];
__device__ __nv_bfloat16 g_wp_l[(size_t)VV * 512];
__device__ __nv_bfloat16 g_hs_h[512 * 512];      // padded to 512 rows (zeros)
__device__ __nv_bfloat16 g_hs_l[512 * 512];
__device__ __nv_bfloat16 g_sent_h[(size_t)512 * VV];  // sent padded to 512 rows
__device__ __nv_bfloat16 g_sent_l[(size_t)512 * VV];
__device__ __nv_bfloat16 g_we_h[(size_t)512 * VV];    // W_e [512, 32000]
__device__ __nv_bfloat16 g_we_l[(size_t)512 * VV];

// ---------------- f32x2 helpers (rnn) ----------------
__device__ __forceinline__ void fma2(unsigned long long& d, unsigned long long a,
                                     unsigned long long b) {
    asm("fma.rn.f32x2 %0, %1, %2, %0;" : "+l"(d) : "l"(a), "l"(b));
}
__device__ __forceinline__ float2 unpack2(unsigned long long d) {
    float2 r;
    asm("mov.b64 {%0, %1}, %2;" : "=f"(r.x), "=f"(r.y) : "l"(d));
    return r;
}

// ---------------- reduce split-K partials into emb ----------------
__global__ void reduce_emb_kernel()
{
    int i = blockIdx.x * 256 + threadIdx.x;
    if (i >= TT * EE) return;
    float s = 0.f;
#pragma unroll
    for (int p = 0; p < SPLITS1; p++) s += g_part[p * (512 * 512) + i];
    g_emb[i] = s;
}

// ---------------- xproj = emb @ W_x^T + b ----------------
__global__ void __launch_bounds__(256)
xproj_kernel(const float* __restrict__ W_x, const float* __restrict__ bias)
{
    __shared__ float As[16][68];
    __shared__ float Bs[16][68];
    const int tid = threadIdx.x;
    const int nt = blockIdx.x, mt = blockIdx.y;
    const int ty = tid >> 4, tx = tid & 15;
    const int m0 = ty * 4, n0 = tx * 4;
    float acc[4][4] = {};

    for (int kb = 0; kb < 512; kb += 16) {
        int m = tid >> 2, k4 = (tid & 3) << 2;
        float4 va = make_float4(0.f, 0.f, 0.f, 0.f);
        int ra = mt * 64 + m;
        if (ra < TT) va = *(const float4*)(g_emb + (size_t)ra * 512 + kb + k4);
        As[k4 + 0][m] = va.x; As[k4 + 1][m] = va.y;
        As[k4 + 2][m] = va.z; As[k4 + 3][m] = va.w;
        float4 vb = *(const float4*)(W_x + (size_t)(nt * 64 + m) * 512 + kb + k4);
        Bs[k4 + 0][m] = vb.x; Bs[k4 + 1][m] = vb.y;
        Bs[k4 + 2][m] = vb.z; Bs[k4 + 3][m] = vb.w;
        __syncthreads();
#pragma unroll
        for (int k = 0; k < 16; k++) {
            float4 a = *(const float4*)&As[k][m0];
            float4 b = *(const float4*)&Bs[k][n0];
            float aa[4] = {a.x, a.y, a.z, a.w};
            float bb[4] = {b.x, b.y, b.z, b.w};
#pragma unroll
            for (int i = 0; i < 4; i++)
#pragma unroll
                for (int j = 0; j < 4; j++) acc[i][j] += aa[i] * bb[j];
        }
        __syncthreads();
    }
#pragma unroll
    for (int i = 0; i < 4; i++) {
        int r = mt * 64 + m0 + i;
        if (r >= TT) continue;
#pragma unroll
        for (int j = 0; j < 4; j++) {
            int col = nt * 64 + n0 + j;
            g_xproj[(size_t)r * 512 + col] = acc[i][j] + bias[col];
        }
    }
}

// ---------------- Elman recurrence: R1 structure, partitioned [t0, t1) ----------
// h state hands off through g_hs[t0-1]; arithmetic identical to the monolithic
// version (same per-step sequence), so hs is byte-identical.
__global__ void __cluster_dims__(8, 1, 1) __launch_bounds__(1024, 1)
rnn_kernel(const float* __restrict__ W_h, int t0, int t1)
{
    __shared__ float hbuf[2][512];
    __shared__ float pbuf[64][17];
    const int tid = threadIdx.x;
    const int w = tid >> 5, l = tid & 31;
    const int g = w & 1, s = w >> 1;
    const int c = (int)blockIdx.x;
    const int row = c * 64 + g * 32 + l;
    const int kbase = s * 32;

    ulonglong2 wv[8];
    {
        const ulonglong2* wp = (const ulonglong2*)(W_h + (size_t)row * 512 + kbase);
#pragma unroll
        for (int j = 0; j < 8; j++) wv[j] = wp[j];
    }
    for (int i = tid; i < 512; i += 1024)
        hbuf[0][i] = (t0 == 0) ? 0.f : g_hs[(size_t)(t0 - 1) * 512 + i];

    uint32_t hbase_local = (uint32_t)__cvta_generic_to_shared(&hbuf[0][0]);
    uint32_t peer[8];
#pragma unroll
    for (int p = 0; p < 8; p++)
        asm("mapa.shared::cluster.u32 %0, %1, %2;" : "=r"(peer[p]) : "r"(hbase_local), "r"(p));

    float xp = (tid < 64) ? g_xproj[(size_t)t0 * 512 + c * 64 + tid] : 0.f;

    __syncthreads();
    asm volatile("barrier.cluster.arrive.aligned;" ::: "memory");
    asm volatile("barrier.cluster.wait.aligned;" ::: "memory");

    for (int t = t0; t < t1; t++) {
        const int cur = (t - t0) & 1;
        const ulonglong2* hp = (const ulonglong2*)&hbuf[cur][kbase];
        unsigned long long acc = 0ull;
#pragma unroll
        for (int j = 0; j < 8; j++) {
            ulonglong2 hh = hp[j];
            fma2(acc, wv[j].x, hh.x);
            fma2(acc, wv[j].y, hh.y);
        }
        float2 f = unpack2(acc);
        pbuf[g * 32 + l][s] = f.x + f.y;
        __syncthreads();
        if (tid < 64) {
            float x = xp;
#pragma unroll
            for (int s2 = 0; s2 < 16; s2++) x += pbuf[tid][s2];
            float h = 1.f / (1.f + __expf(-x));
            g_hs[(size_t)t * 512 + c * 64 + tid] = h;
            uint32_t off = (uint32_t)(((cur ^ 1) * 512 + c * 64 + tid) * 4);
#pragma unroll
            for (int p = 0; p < 8; p++)
                asm volatile("st.shared::cluster.f32 [%0], %1;"
                             :: "r"(peer[p] + off), "f"(h) : "memory");
            int tn = (t + 1 < t1) ? (t + 1) : t;
            xp = g_xproj[(size_t)tn * 512 + c * 64 + tid];
        }
        asm volatile("barrier.cluster.arrive.aligned;" ::: "memory");
        asm volatile("barrier.cluster.wait.aligned;" ::: "memory");
    }
}

// ---------------- bf16 hi/lo split preps ----------------
__global__ void prep_wp_kernel(const float* __restrict__ W_p)
{
    size_t i = (size_t)blockIdx.x * 1024 + threadIdx.x;
    if (i >= (size_t)VV * 512) return;
    float v = W_p[i];
    __nv_bfloat16 h = __float2bfloat16_rn(v);
    g_wp_h[i] = h;
    g_wp_l[i] = __float2bfloat16_rn(v - __bfloat162float(h));
}
// per-tile hs split: covers elements [elemBase, elemBase + 65536)
__global__ void prep_hs_kernel(int elemBase)
{
    int i = elemBase + blockIdx.x * 1024 + threadIdx.x;
    float v = (i < TT * 512) ? g_hs[i] : 0.f;
    __nv_bfloat16 h = __float2bfloat16_rn(v);
    g_hs_h[i] = h;
    g_hs_l[i] = __float2bfloat16_rn(v - __bfloat162float(h));
}
__global__ void prep_sent_kernel(const float* __restrict__ sent)
{
    size_t i = (size_t)blockIdx.x * 1024 + threadIdx.x;
    if (i >= (size_t)512 * VV) return;
    float v = (i < (size_t)TT * VV) ? sent[i] : 0.f;   // pad row 511 with zeros
    __nv_bfloat16 h = __float2bfloat16_rn(v);
    g_sent_h[i] = h;
    g_sent_l[i] = __float2bfloat16_rn(v - __bfloat162float(h));
}
__global__ void prep_we_kernel(const float* __restrict__ W_e)
{
    size_t i = (size_t)blockIdx.x * 1024 + threadIdx.x;
    if (i >= (size_t)512 * VV) return;
    float v = W_e[i];
    __nv_bfloat16 h = __float2bfloat16_rn(v);
    g_we_h[i] = h;
    g_we_l[i] = __float2bfloat16_rn(v - __bfloat162float(h));
}

// ---------------- generic WMMA bf16 3-pass GEMM, occ 2 --------------------------
// C[m,n] = sum_k A[m,k]*B[n,k], both K-major, hi/lo bf16 splits, 3 passes.
// CTA tile 128(M) x 128(N), 8 warps 2x4, warp tile 64x32 (4x2 m16n16k16 frags).
// K chunks of 32, depth-2 cp.async pipeline. Smem 2 x 49152 B -> 2 CTAs/SM.
// Split-K via blockIdx.z; mBase/nBase allow M/N sub-tiling across launches.
#define G2_LD 48
#define G2_A_SZ (128 * G2_LD)                        // elems per split (A or B)
#define G2_BUF_ELEMS (4 * G2_A_SZ)                   // Ah,Al,Bh,Bl = 24576 elems
#define G2_SMEM (2 * G2_BUF_ELEMS * 2)               // 98304 bytes

__device__ __forceinline__ void cp_async16(uint32_t dst, const void* src) {
    asm volatile("cp.async.cg.shared.global [%0], [%1], 16;"
                 :: "r"(dst), "l"(src));
}

__global__ void __launch_bounds__(256, 2)
gemm_wmma3(const __nv_bfloat16* __restrict__ Ah_g, const __nv_bfloat16* __restrict__ Al_g,
           int lda,
           const __nv_bfloat16* __restrict__ Bh_g, const __nv_bfloat16* __restrict__ Bl_g,
           int ldb,
           float* __restrict__ C, int ldc, size_t zStride, int kPerSplit,
           int mBase, int nBase)
{
    extern __shared__ __align__(32) __nv_bfloat16 sm2[];
    const uint32_t sbase = (uint32_t)__cvta_generic_to_shared(sm2);
    const __nv_bfloat16* Agm[2] = { Ah_g, Al_g };
    const __nv_bfloat16* Bgm[2] = { Bh_g, Bl_g };

    const int tid = threadIdx.x;
    const int wid = tid >> 5;
    const int warp_m = wid >> 2;          // 0..1  (64-row halves)
    const int warp_n = wid & 3;           // 0..3  (32-col quarters)
    const int nt = blockIdx.x, mt = blockIdx.y, sz = blockIdx.z;
    const int arow = mBase + mt * 128, brow = (nBase + nt) * 128;
    const int kOff = sz * kPerSplit;
    const int nChunks = kPerSplit >> 5;
    float* Cz = C + (size_t)sz * zStride;

    int a_off[4], b_off[4];
    const __nv_bfloat16* a_src[4];
    const __nv_bfloat16* b_src[4];
#pragma unroll
    for (int i = 0; i < 4; i++) {
        int lin = tid + i * 256;
        int s = lin >> 9, rem = lin & 511;
        int r = rem >> 2, seg = rem & 3;
        a_off[i] = s * G2_A_SZ + r * G2_LD + seg * 8;
        a_src[i] = Agm[s] + (size_t)(arow + r) * lda + kOff + seg * 8;
        b_off[i] = (2 + s) * G2_A_SZ + r * G2_LD + seg * 8;
        b_src[i] = Bgm[s] + (size_t)(brow + r) * ldb + kOff + seg * 8;
    }

    auto issue_chunk = [&](int buf, int kc) {
        uint32_t base = sbase + (uint32_t)(buf * G2_BUF_ELEMS) * 2;
#pragma unroll
        for (int i = 0; i < 4; i++) {
            cp_async16(base + (uint32_t)a_off[i] * 2, a_src[i] + kc);
            cp_async16(base + (uint32_t)b_off[i] * 2, b_src[i] + kc);
        }
        asm volatile("cp.async.commit_group;" ::: "memory");
    };

    wmma::fragment<wmma::accumulator, 16, 16, 16, float> acc[4][2];
#pragma unroll
    for (int mi = 0; mi < 4; mi++)
#pragma unroll
        for (int ni = 0; ni < 2; ni++) wmma::fill_fragment(acc[mi][ni], 0.f);

    issue_chunk(0, 0);
    if (nChunks > 1) issue_chunk(1, 32);

    for (int c = 0; c < nChunks; c++) {
        const int buf = c & 1;
        if (c + 2 < nChunks)
            asm volatile("cp.async.wait_group 1;" ::: "memory");
        else
            asm volatile("cp.async.wait_group 0;" ::: "memory");
        __syncthreads();

        __nv_bfloat16* A0 = sm2 + buf * G2_BUF_ELEMS;
        __nv_bfloat16* B0 = A0 + 2 * G2_A_SZ;
#pragma unroll
        for (int kk = 0; kk < 2; kk++) {
            const int k0 = kk * 16;
#pragma unroll
            for (int p = 0; p < 3; p++) {           // (hi,hi), (hi,lo), (lo,hi)
                const int pa = (p == 2) ? 1 : 0;
                const int pb = (p == 1) ? 1 : 0;
                wmma::fragment<wmma::matrix_a, 16, 16, 16, __nv_bfloat16, wmma::row_major> af[4];
                wmma::fragment<wmma::matrix_b, 16, 16, 16, __nv_bfloat16, wmma::col_major> bf[2];
#pragma unroll
                for (int mi = 0; mi < 4; mi++)
                    wmma::load_matrix_sync(af[mi],
                        A0 + pa * G2_A_SZ + (warp_m * 64 + mi * 16) * G2_LD + k0, G2_LD);
#pragma unroll
                for (int ni = 0; ni < 2; ni++)
                    wmma::load_matrix_sync(bf[ni],
                        B0 + pb * G2_A_SZ + (warp_n * 32 + ni * 16) * G2_LD + k0, G2_LD);
#pragma unroll
                for (int mi = 0; mi < 4; mi++)
#pragma unroll
                    for (int ni = 0; ni < 2; ni++)
                        wmma::mma_sync(acc[mi][ni], af[mi], bf[ni], acc[mi][ni]);
            }
        }
        __syncthreads();
        if (c + 2 < nChunks)
            issue_chunk(buf, (c + 2) * 32);
    }

#pragma unroll
    for (int mi = 0; mi < 4; mi++)
#pragma unroll
        for (int ni = 0; ni < 2; ni++) {
            int m = arow + warp_m * 64 + mi * 16;
            int n = brow + warp_n * 32 + ni * 16;
            wmma::store_matrix_sync(Cz + (size_t)m * ldc + n, acc[mi][ni], ldc,
                                    wmma::mem_row_major);
        }
}

// ---------------- fused single-pass row softmax over V=32000 ----------------
__global__ void __launch_bounds__(512)
softmax_kernel(float* __restrict__ out, int rowBase)
{
    extern __shared__ float buf[];                     // 32000 floats
    __shared__ float red[512];
    const int t = rowBase + blockIdx.x;
    const int tid = threadIdx.x;
    const float4* r4 = (const float4*)(g_logits + (size_t)t * VV);
    float4* b4 = (float4*)buf;
    float4* o4 = (float4*)(out + (size_t)t * VV);

    float mx = -3.402823466e38f;
    for (int i = tid; i < VV / 4; i += 512) {
        float4 v = r4[i];
        b4[i] = v;
        mx = fmaxf(mx, fmaxf(fmaxf(v.x, v.y), fmaxf(v.z, v.w)));
    }
    red[tid] = mx; __syncthreads();
    for (int o = 256; o > 0; o >>= 1) {
        if (tid < o) red[tid] = fmaxf(red[tid], red[tid + o]);
        __syncthreads();
    }
    mx = red[0]; __syncthreads();

    float sum = 0.f;
    for (int i = tid; i < VV / 4; i += 512) {
        float4 v = b4[i];
        v.x = __expf(v.x - mx); v.y = __expf(v.y - mx);
        v.z = __expf(v.z - mx); v.w = __expf(v.w - mx);
        b4[i] = v;
        sum += (v.x + v.y) + (v.z + v.w);
    }
    red[tid] = sum; __syncthreads();
    for (int o = 256; o > 0; o >>= 1) {
        if (tid < o) red[tid] += red[tid + o];
        __syncthreads();
    }
    float inv = 1.f / red[0];

    for (int i = tid; i < VV / 4; i += 512) {
        float4 v = b4[i];
        v.x *= inv; v.y *= inv; v.z *= inv; v.w *= inv;
        o4[i] = v;
    }
}

// ---------------- launch: rnn pipelined against gemm2/softmax tiles -------------
extern "C" void kernel_launch(void* const* d_in, const int* in_sizes, int n_in,
                              void* d_out, int out_size)
{
    const float* sent = (const float*)d_in[0];
    const float* W_e  = (const float*)d_in[1];
    const float* W_x  = (const float*)d_in[2];
    const float* W_h  = (const float*)d_in[3];
    const float* W_p  = (const float*)d_in[4];
    const float* b    = (const float*)d_in[5];
    float* out = (float*)d_out;

    float *part, *logits;
    __nv_bfloat16 *sh, *sl, *wh, *wl, *hh, *hl, *ph, *pl;
    cudaGetSymbolAddress((void**)&part,   g_part);
    cudaGetSymbolAddress((void**)&logits, g_logits);
    cudaGetSymbolAddress((void**)&sh, g_sent_h);
    cudaGetSymbolAddress((void**)&sl, g_sent_l);
    cudaGetSymbolAddress((void**)&wh, g_we_h);
    cudaGetSymbolAddress((void**)&wl, g_we_l);
    cudaGetSymbolAddress((void**)&hh, g_hs_h);
    cudaGetSymbolAddress((void**)&hl, g_hs_l);
    cudaGetSymbolAddress((void**)&ph, g_wp_h);
    cudaGetSymbolAddress((void**)&pl, g_wp_l);

    cudaFuncSetAttribute(softmax_kernel,
                         cudaFuncAttributeMaxDynamicSharedMemorySize, VV * 4);
    cudaFuncSetAttribute(gemm_wmma3,
                         cudaFuncAttributeMaxDynamicSharedMemorySize, G2_SMEM);

    // side stream + events, created ONCE (outside any capture; work per call
    // is identical every time — no device allocation inside kernel_launch calls
    // after the first).
    static cudaStream_t side = nullptr;
    static cudaEvent_t ev0 = nullptr, evp[4], evj = nullptr;
    if (!side) {
        cudaStreamCreateWithFlags(&side, cudaStreamNonBlocking);
        cudaEventCreateWithFlags(&ev0, cudaEventDisableTiming);
        for (int m = 0; m < 4; m++)
            cudaEventCreateWithFlags(&evp[m], cudaEventDisableTiming);
        cudaEventCreateWithFlags(&evj, cudaEventDisableTiming);
    }

    // fork side stream at the very start; prep_wp hides under gemm1
    cudaEventRecord(ev0, 0);
    cudaStreamWaitEvent(side, ev0, 0);
    const int nPrep = (512 * VV + 1023) / 1024;
    prep_wp_kernel<<<nPrep, 1024, 0, side>>>(W_p);

    // main chain up to rnn
    prep_sent_kernel<<<nPrep, 1024>>>(sent);
    prep_we_kernel<<<nPrep, 1024>>>(W_e);
    gemm_wmma3<<<dim3(4, 4, SPLITS1), 256, G2_SMEM>>>(
        sh, sl, VV, wh, wl, VV, part, 512, (size_t)512 * 512, KSPLIT1, 0, 0);
    reduce_emb_kernel<<<(TT * EE + 255) / 256, 256>>>();
    xproj_kernel<<<dim3(8, 8), 256>>>(W_x, b);

    // rnn parts pipelined against per-tile prep_hs + gemm2 + softmax on side
    const int bounds[5] = {0, 128, 256, 384, TT};
    for (int m = 0; m < 4; m++) {
        rnn_kernel<<<8, 1024>>>(W_h, bounds[m], bounds[m + 1]);
        cudaEventRecord(evp[m], 0);
        cudaStreamWaitEvent(side, evp[m], 0);
        // split hs rows [128m, 128m+128) (tile 3 zero-pads row 511)
        prep_hs_kernel<<<64, 1024, 0, side>>>(m * 128 * 512);
        // logits rows of this tile: two half-N launches keep >=85 SMs free
        gemm_wmma3<<<dim3(125, 1, 1), 256, G2_SMEM, side>>>(
            hh, hl, 512, ph, pl, 512, logits, VV, 0, 512, m * 128, 0);
        gemm_wmma3<<<dim3(125, 1, 1), 256, G2_SMEM, side>>>(
            hh, hl, 512, ph, pl, 512, logits, VV, 0, 512, m * 128, 125);
        // softmax this tile's rows
        softmax_kernel<<<bounds[m + 1] - bounds[m], 512, VV * 4, side>>>(
            out, bounds[m]);
    }

    // join side stream back into the main (capture) stream
    cudaEventRecord(evj, side);
    cudaStreamWaitEvent(0, evj, 0);
}

// round 15
// speedup vs baseline: 1.3493x; 1.0674x over previous
#include <cuda_runtime.h>
#include <cuda_bf16.h>
#include <mma.h>
#include <cstdint>
#include <cstddef>

using namespace nvcuda;

#define TT 511          // T-1 rows
#define VV 32000
#define EE 512
#define HH 512
#define SPLITS1 40      // split-K factor for GEMM1 (K=32000 -> 800 per split)
#define KSPLIT1 800

// ---------------- scratch (__device__ globals; no allocation) ----------------
__device__ float g_part[SPLITS1 * 512 * 512];
__device__ float g_emb[TT * EE];
__device__ float g_xproj[TT * HH];
__device__ float g_hs[TT * HH];
__device__ float g_logits[(size_t)512 * VV];     // padded to 512 rows for wmma store
__device__ __nv_bfloat16 g_wp_h[(size_t)VV * 512];
__device__ __nv_bfloat16 g_wp_l[(size_t)VV * 512];
__device__ __nv_bfloat16 g_hs_h[512 * 512];      // padded to 512 rows (zeros)
__device__ __nv_bfloat16 g_hs_l[512 * 512];
__device__ __nv_bfloat16 g_sent_h[(size_t)512 * VV];  // sent padded to 512 rows
__device__ __nv_bfloat16 g_sent_l[(size_t)512 * VV];
__device__ __nv_bfloat16 g_we_h[(size_t)512 * VV];    // W_e [512, 32000]
__device__ __nv_bfloat16 g_we_l[(size_t)512 * VV];

// ---------------- f32x2 helpers (rnn) ----------------
__device__ __forceinline__ void fma2(unsigned long long& d, unsigned long long a,
                                     unsigned long long b) {
    asm("fma.rn.f32x2 %0, %1, %2, %0;" : "+l"(d) : "l"(a), "l"(b));
}
__device__ __forceinline__ float2 unpack2(unsigned long long d) {
    float2 r;
    asm("mov.b64 {%0, %1}, %2;" : "=f"(r.x), "=f"(r.y) : "l"(d));
    return r;
}

// ---------------- reduce split-K partials into emb ----------------
__global__ void reduce_emb_kernel()
{
    int i = blockIdx.x * 256 + threadIdx.x;
    if (i >= TT * EE) return;
    float s = 0.f;
#pragma unroll
    for (int p = 0; p < SPLITS1; p++) s += g_part[p * (512 * 512) + i];
    g_emb[i] = s;
}

// ---------------- xproj = emb @ W_x^T + b ----------------
__global__ void __launch_bounds__(256)
xproj_kernel(const float* __restrict__ W_x, const float* __restrict__ bias)
{
    __shared__ float As[16][68];
    __shared__ float Bs[16][68];
    const int tid = threadIdx.x;
    const int nt = blockIdx.x, mt = blockIdx.y;
    const int ty = tid >> 4, tx = tid & 15;
    const int m0 = ty * 4, n0 = tx * 4;
    float acc[4][4] = {};

    for (int kb = 0; kb < 512; kb += 16) {
        int m = tid >> 2, k4 = (tid & 3) << 2;
        float4 va = make_float4(0.f, 0.f, 0.f, 0.f);
        int ra = mt * 64 + m;
        if (ra < TT) va = *(const float4*)(g_emb + (size_t)ra * 512 + kb + k4);
        As[k4 + 0][m] = va.x; As[k4 + 1][m] = va.y;
        As[k4 + 2][m] = va.z; As[k4 + 3][m] = va.w;
        float4 vb = *(const float4*)(W_x + (size_t)(nt * 64 + m) * 512 + kb + k4);
        Bs[k4 + 0][m] = vb.x; Bs[k4 + 1][m] = vb.y;
        Bs[k4 + 2][m] = vb.z; Bs[k4 + 3][m] = vb.w;
        __syncthreads();
#pragma unroll
        for (int k = 0; k < 16; k++) {
            float4 a = *(const float4*)&As[k][m0];
            float4 b = *(const float4*)&Bs[k][n0];
            float aa[4] = {a.x, a.y, a.z, a.w};
            float bb[4] = {b.x, b.y, b.z, b.w};
#pragma unroll
            for (int i = 0; i < 4; i++)
#pragma unroll
                for (int j = 0; j < 4; j++) acc[i][j] += aa[i] * bb[j];
        }
        __syncthreads();
    }
#pragma unroll
    for (int i = 0; i < 4; i++) {
        int r = mt * 64 + m0 + i;
        if (r >= TT) continue;
#pragma unroll
        for (int j = 0; j < 4; j++) {
            int col = nt * 64 + n0 + j;
            g_xproj[(size_t)r * 512 + col] = acc[i][j] + bias[col];
        }
    }
}

// ---------------- Elman recurrence: R1 structure + SMEM xproj slice -------------
// Partitioned [t0, t1); h hands off through g_hs[t0-1]. The part's xproj slice
// is preloaded into dynamic SMEM so the per-step xp read is a 29-cyc LDS,
// immune to side-stream L2 pressure. Arithmetic identical -> hs byte-identical.
__global__ void __cluster_dims__(8, 1, 1) __launch_bounds__(1024, 1)
rnn_kernel(const float* __restrict__ W_h, int t0, int t1)
{
    extern __shared__ float xps[];                 // [(t1-t0) * 64]
    __shared__ float hbuf[2][512];
    __shared__ float pbuf[64][17];
    const int tid = threadIdx.x;
    const int w = tid >> 5, l = tid & 31;
    const int g = w & 1, s = w >> 1;
    const int c = (int)blockIdx.x;
    const int row = c * 64 + g * 32 + l;
    const int kbase = s * 32;

    ulonglong2 wv[8];
    {
        const ulonglong2* wp = (const ulonglong2*)(W_h + (size_t)row * 512 + kbase);
#pragma unroll
        for (int j = 0; j < 8; j++) wv[j] = wp[j];
    }
    for (int i = tid; i < 512; i += 1024)
        hbuf[0][i] = (t0 == 0) ? 0.f : g_hs[(size_t)(t0 - 1) * 512 + i];

    const int nloc = (t1 - t0) * 64;
    for (int i = tid; i < nloc; i += 1024)
        xps[i] = g_xproj[(size_t)(t0 + (i >> 6)) * 512 + c * 64 + (i & 63)];

    uint32_t hbase_local = (uint32_t)__cvta_generic_to_shared(&hbuf[0][0]);
    uint32_t peer[8];
#pragma unroll
    for (int p = 0; p < 8; p++)
        asm("mapa.shared::cluster.u32 %0, %1, %2;" : "=r"(peer[p]) : "r"(hbase_local), "r"(p));

    __syncthreads();
    asm volatile("barrier.cluster.arrive.aligned;" ::: "memory");
    asm volatile("barrier.cluster.wait.aligned;" ::: "memory");

    for (int t = t0; t < t1; t++) {
        const int cur = (t - t0) & 1;
        const ulonglong2* hp = (const ulonglong2*)&hbuf[cur][kbase];
        unsigned long long acc = 0ull;
#pragma unroll
        for (int j = 0; j < 8; j++) {
            ulonglong2 hh = hp[j];
            fma2(acc, wv[j].x, hh.x);
            fma2(acc, wv[j].y, hh.y);
        }
        float2 f = unpack2(acc);
        pbuf[g * 32 + l][s] = f.x + f.y;
        __syncthreads();
        if (tid < 64) {
            float x = xps[(t - t0) * 64 + tid];
#pragma unroll
            for (int s2 = 0; s2 < 16; s2++) x += pbuf[tid][s2];
            float h = 1.f / (1.f + __expf(-x));
            g_hs[(size_t)t * 512 + c * 64 + tid] = h;
            uint32_t off = (uint32_t)(((cur ^ 1) * 512 + c * 64 + tid) * 4);
#pragma unroll
            for (int p = 0; p < 8; p++)
                asm volatile("st.shared::cluster.f32 [%0], %1;"
                             :: "r"(peer[p] + off), "f"(h) : "memory");
        }
        asm volatile("barrier.cluster.arrive.aligned;" ::: "memory");
        asm volatile("barrier.cluster.wait.aligned;" ::: "memory");
    }
}

// ---------------- bf16 hi/lo split preps ----------------
__global__ void prep_wp_kernel(const float* __restrict__ W_p)
{
    size_t i = (size_t)blockIdx.x * 1024 + threadIdx.x;
    if (i >= (size_t)VV * 512) return;
    float v = W_p[i];
    __nv_bfloat16 h = __float2bfloat16_rn(v);
    g_wp_h[i] = h;
    g_wp_l[i] = __float2bfloat16_rn(v - __bfloat162float(h));
}
// per-tile hs split: covers elements [elemBase, elemBase + 65536)
__global__ void prep_hs_kernel(int elemBase)
{
    int i = elemBase + blockIdx.x * 1024 + threadIdx.x;
    float v = (i < TT * 512) ? g_hs[i] : 0.f;
    __nv_bfloat16 h = __float2bfloat16_rn(v);
    g_hs_h[i] = h;
    g_hs_l[i] = __float2bfloat16_rn(v - __bfloat162float(h));
}
// combined sent + W_e split (one launch, full-BW)
__global__ void prep_sentwe_kernel(const float* __restrict__ sent,
                                   const float* __restrict__ W_e)
{
    size_t i = (size_t)blockIdx.x * 1024 + threadIdx.x;
    const size_t N = (size_t)512 * VV;
    if (i < N) {
        float v = (i < (size_t)TT * VV) ? sent[i] : 0.f;   // pad row 511
        __nv_bfloat16 h = __float2bfloat16_rn(v);
        g_sent_h[i] = h;
        g_sent_l[i] = __float2bfloat16_rn(v - __bfloat162float(h));
    } else if (i < 2 * N) {
        size_t j = i - N;
        float v = W_e[j];
        __nv_bfloat16 h = __float2bfloat16_rn(v);
        g_we_h[j] = h;
        g_we_l[j] = __float2bfloat16_rn(v - __bfloat162float(h));
    }
}

// ---------------- generic WMMA bf16 3-pass GEMM, occ 2 --------------------------
#define G2_LD 48
#define G2_A_SZ (128 * G2_LD)                        // elems per split (A or B)
#define G2_BUF_ELEMS (4 * G2_A_SZ)                   // Ah,Al,Bh,Bl = 24576 elems
#define G2_SMEM (2 * G2_BUF_ELEMS * 2)               // 98304 bytes

__device__ __forceinline__ void cp_async16(uint32_t dst, const void* src) {
    asm volatile("cp.async.cg.shared.global [%0], [%1], 16;"
                 :: "r"(dst), "l"(src));
}

__global__ void __launch_bounds__(256, 2)
gemm_wmma3(const __nv_bfloat16* __restrict__ Ah_g, const __nv_bfloat16* __restrict__ Al_g,
           int lda,
           const __nv_bfloat16* __restrict__ Bh_g, const __nv_bfloat16* __restrict__ Bl_g,
           int ldb,
           float* __restrict__ C, int ldc, size_t zStride, int kPerSplit,
           int mBase, int nBase)
{
    extern __shared__ __align__(32) __nv_bfloat16 sm2[];
    const uint32_t sbase = (uint32_t)__cvta_generic_to_shared(sm2);
    const __nv_bfloat16* Agm[2] = { Ah_g, Al_g };
    const __nv_bfloat16* Bgm[2] = { Bh_g, Bl_g };

    const int tid = threadIdx.x;
    const int wid = tid >> 5;
    const int warp_m = wid >> 2;          // 0..1  (64-row halves)
    const int warp_n = wid & 3;           // 0..3  (32-col quarters)
    const int nt = blockIdx.x, mt = blockIdx.y, sz = blockIdx.z;
    const int arow = mBase + mt * 128, brow = (nBase + nt) * 128;
    const int kOff = sz * kPerSplit;
    const int nChunks = kPerSplit >> 5;
    float* Cz = C + (size_t)sz * zStride;

    int a_off[4], b_off[4];
    const __nv_bfloat16* a_src[4];
    const __nv_bfloat16* b_src[4];
#pragma unroll
    for (int i = 0; i < 4; i++) {
        int lin = tid + i * 256;
        int s = lin >> 9, rem = lin & 511;
        int r = rem >> 2, seg = rem & 3;
        a_off[i] = s * G2_A_SZ + r * G2_LD + seg * 8;
        a_src[i] = Agm[s] + (size_t)(arow + r) * lda + kOff + seg * 8;
        b_off[i] = (2 + s) * G2_A_SZ + r * G2_LD + seg * 8;
        b_src[i] = Bgm[s] + (size_t)(brow + r) * ldb + kOff + seg * 8;
    }

    auto issue_chunk = [&](int buf, int kc) {
        uint32_t base = sbase + (uint32_t)(buf * G2_BUF_ELEMS) * 2;
#pragma unroll
        for (int i = 0; i < 4; i++) {
            cp_async16(base + (uint32_t)a_off[i] * 2, a_src[i] + kc);
            cp_async16(base + (uint32_t)b_off[i] * 2, b_src[i] + kc);
        }
        asm volatile("cp.async.commit_group;" ::: "memory");
    };

    wmma::fragment<wmma::accumulator, 16, 16, 16, float> acc[4][2];
#pragma unroll
    for (int mi = 0; mi < 4; mi++)
#pragma unroll
        for (int ni = 0; ni < 2; ni++) wmma::fill_fragment(acc[mi][ni], 0.f);

    issue_chunk(0, 0);
    if (nChunks > 1) issue_chunk(1, 32);

    for (int c = 0; c < nChunks; c++) {
        const int buf = c & 1;
        if (c + 2 < nChunks)
            asm volatile("cp.async.wait_group 1;" ::: "memory");
        else
            asm volatile("cp.async.wait_group 0;" ::: "memory");
        __syncthreads();

        __nv_bfloat16* A0 = sm2 + buf * G2_BUF_ELEMS;
        __nv_bfloat16* B0 = A0 + 2 * G2_A_SZ;
#pragma unroll
        for (int kk = 0; kk < 2; kk++) {
            const int k0 = kk * 16;
#pragma unroll
            for (int p = 0; p < 3; p++) {           // (hi,hi), (hi,lo), (lo,hi)
                const int pa = (p == 2) ? 1 : 0;
                const int pb = (p == 1) ? 1 : 0;
                wmma::fragment<wmma::matrix_a, 16, 16, 16, __nv_bfloat16, wmma::row_major> af[4];
                wmma::fragment<wmma::matrix_b, 16, 16, 16, __nv_bfloat16, wmma::col_major> bf[2];
#pragma unroll
                for (int mi = 0; mi < 4; mi++)
                    wmma::load_matrix_sync(af[mi],
                        A0 + pa * G2_A_SZ + (warp_m * 64 + mi * 16) * G2_LD + k0, G2_LD);
#pragma unroll
                for (int ni = 0; ni < 2; ni++)
                    wmma::load_matrix_sync(bf[ni],
                        B0 + pb * G2_A_SZ + (warp_n * 32 + ni * 16) * G2_LD + k0, G2_LD);
#pragma unroll
                for (int mi = 0; mi < 4; mi++)
#pragma unroll
                    for (int ni = 0; ni < 2; ni++)
                        wmma::mma_sync(acc[mi][ni], af[mi], bf[ni], acc[mi][ni]);
            }
        }
        __syncthreads();
        if (c + 2 < nChunks)
            issue_chunk(buf, (c + 2) * 32);
    }

#pragma unroll
    for (int mi = 0; mi < 4; mi++)
#pragma unroll
        for (int ni = 0; ni < 2; ni++) {
            int m = arow + warp_m * 64 + mi * 16;
            int n = brow + warp_n * 32 + ni * 16;
            wmma::store_matrix_sync(Cz + (size_t)m * ldc + n, acc[mi][ni], ldc,
                                    wmma::mem_row_major);
        }
}

// ---------------- fused single-pass row softmax over V=32000 ----------------
__global__ void __launch_bounds__(512)
softmax_kernel(float* __restrict__ out, int rowBase)
{
    extern __shared__ float buf[];                     // 32000 floats
    __shared__ float red[512];
    const int t = rowBase + blockIdx.x;
    const int tid = threadIdx.x;
    const float4* r4 = (const float4*)(g_logits + (size_t)t * VV);
    float4* b4 = (float4*)buf;
    float4* o4 = (float4*)(out + (size_t)t * VV);

    float mx = -3.402823466e38f;
    for (int i = tid; i < VV / 4; i += 512) {
        float4 v = r4[i];
        b4[i] = v;
        mx = fmaxf(mx, fmaxf(fmaxf(v.x, v.y), fmaxf(v.z, v.w)));
    }
    red[tid] = mx; __syncthreads();
    for (int o = 256; o > 0; o >>= 1) {
        if (tid < o) red[tid] = fmaxf(red[tid], red[tid + o]);
        __syncthreads();
    }
    mx = red[0]; __syncthreads();

    float sum = 0.f;
    for (int i = tid; i < VV / 4; i += 512) {
        float4 v = b4[i];
        v.x = __expf(v.x - mx); v.y = __expf(v.y - mx);
        v.z = __expf(v.z - mx); v.w = __expf(v.w - mx);
        b4[i] = v;
        sum += (v.x + v.y) + (v.z + v.w);
    }
    red[tid] = sum; __syncthreads();
    for (int o = 256; o > 0; o >>= 1) {
        if (tid < o) red[tid] += red[tid + o];
        __syncthreads();
    }
    float inv = 1.f / red[0];

    for (int i = tid; i < VV / 4; i += 512) {
        float4 v = b4[i];
        v.x *= inv; v.y *= inv; v.z *= inv; v.w *= inv;
        o4[i] = v;
    }
}

// ---------------- launch: rnn pipelined against gemm2/softmax tiles -------------
extern "C" void kernel_launch(void* const* d_in, const int* in_sizes, int n_in,
                              void* d_out, int out_size)
{
    const float* sent = (const float*)d_in[0];
    const float* W_e  = (const float*)d_in[1];
    const float* W_x  = (const float*)d_in[2];
    const float* W_h  = (const float*)d_in[3];
    const float* W_p  = (const float*)d_in[4];
    const float* b    = (const float*)d_in[5];
    float* out = (float*)d_out;

    float *part, *logits;
    __nv_bfloat16 *sh, *sl, *wh, *wl, *hh, *hl, *ph, *pl;
    cudaGetSymbolAddress((void**)&part,   g_part);
    cudaGetSymbolAddress((void**)&logits, g_logits);
    cudaGetSymbolAddress((void**)&sh, g_sent_h);
    cudaGetSymbolAddress((void**)&sl, g_sent_l);
    cudaGetSymbolAddress((void**)&wh, g_we_h);
    cudaGetSymbolAddress((void**)&wl, g_we_l);
    cudaGetSymbolAddress((void**)&hh, g_hs_h);
    cudaGetSymbolAddress((void**)&hl, g_hs_l);
    cudaGetSymbolAddress((void**)&ph, g_wp_h);
    cudaGetSymbolAddress((void**)&pl, g_wp_l);

    cudaFuncSetAttribute(softmax_kernel,
                         cudaFuncAttributeMaxDynamicSharedMemorySize, VV * 4);
    cudaFuncSetAttribute(gemm_wmma3,
                         cudaFuncAttributeMaxDynamicSharedMemorySize, G2_SMEM);
    cudaFuncSetAttribute(rnn_kernel,
                         cudaFuncAttributeMaxDynamicSharedMemorySize, 128 * 64 * 4);

    // side stream + events, created ONCE
    static cudaStream_t side = nullptr;
    static cudaEvent_t ev0 = nullptr, evp[4], evj = nullptr;
    if (!side) {
        cudaStreamCreateWithFlags(&side, cudaStreamNonBlocking);
        cudaEventCreateWithFlags(&ev0, cudaEventDisableTiming);
        for (int m = 0; m < 4; m++)
            cudaEventCreateWithFlags(&evp[m], cudaEventDisableTiming);
        cudaEventCreateWithFlags(&evj, cudaEventDisableTiming);
    }

    // fork side stream at the very start; prep_wp hides under gemm1
    cudaEventRecord(ev0, 0);
    cudaStreamWaitEvent(side, ev0, 0);
    const int nPrep = (512 * VV + 1023) / 1024;
    prep_wp_kernel<<<nPrep, 1024, 0, side>>>(W_p);

    // main chain up to rnn
    prep_sentwe_kernel<<<2 * nPrep, 1024>>>(sent, W_e);
    gemm_wmma3<<<dim3(4, 4, SPLITS1), 256, G2_SMEM>>>(
        sh, sl, VV, wh, wl, VV, part, 512, (size_t)512 * 512, KSPLIT1, 0, 0);
    reduce_emb_kernel<<<(TT * EE + 255) / 256, 256>>>();
    xproj_kernel<<<dim3(8, 8), 256>>>(W_x, b);

    // rnn parts pipelined against per-tile prep_hs + gemm2 + softmax on side
    const int bounds[5] = {0, 128, 256, 384, TT};
    for (int m = 0; m < 4; m++) {
        int len = bounds[m + 1] - bounds[m];
        rnn_kernel<<<8, 1024, len * 64 * 4>>>(W_h, bounds[m], bounds[m + 1]);
        cudaEventRecord(evp[m], 0);
        cudaStreamWaitEvent(side, evp[m], 0);
        prep_hs_kernel<<<64, 1024, 0, side>>>(m * 128 * 512);
        gemm_wmma3<<<dim3(125, 1, 1), 256, G2_SMEM, side>>>(
            hh, hl, 512, ph, pl, 512, logits, VV, 0, 512, m * 128, 0);
        gemm_wmma3<<<dim3(125, 1, 1), 256, G2_SMEM, side>>>(
            hh, hl, 512, ph, pl, 512, logits, VV, 0, 512, m * 128, 125);
        softmax_kernel<<<len, 512, VV * 4, side>>>(out, bounds[m]);
    }

    // join side stream back into the main (capture) stream
    cudaEventRecord(evj, side);
    cudaStreamWaitEvent(0, evj, 0);
}